// round 1
// baseline (speedup 1.0000x reference)
#include <cuda_runtime.h>

#define B_      256
#define N_      1024
#define DIN     64
#define HID     256
#define DOUT    128
#define MT      64           // rows per phi tile
#define TILES   (N_ / MT)    // 16
#define LDX     68           // padded row stride for x tile (floats)
#define LDH     260          // padded row stride for h tiles (floats)

// Dynamic smem layout (in floats):
//  xS  : [64][68]            = 4352
//  hA  : [64][260]           = 16640
//  hB  : [64][260]           = 16640
//  wbuf: [2][16][256]        = 8192   (also reused as 16x256 reduction buffer)
#define OFF_XS   0
#define OFF_HA   4352
#define OFF_HB   (4352 + 16640)
#define OFF_WB   (4352 + 16640 + 16640)
#define SMEM_FLOATS (OFF_WB + 8192)
#define SMEM_BYTES  (SMEM_FLOATS * 4)

// per-tile partial pooled sums: [B][TILES][HID]  (4 MB, static device scratch)
__device__ float g_partial[B_ * TILES * HID];

// ---------------------------------------------------------------------------
// inner MMA: 16 k-steps, thread tile 4(M) x 16(N), operands from smem
// ---------------------------------------------------------------------------
__device__ __forceinline__ void mma_ktile(const float* __restrict__ ws,   // [16][256]
                                          const float* __restrict__ in_s, // [64][ld]
                                          int ld_in, int kbase,
                                          int m0, int n0, float acc[4][16])
{
#pragma unroll
    for (int kk = 0; kk < 16; kk++) {
        const float* wr = ws + kk * 256 + n0;
        float wv[16];
        *(float4*)&wv[0]  = *(const float4*)(wr + 0);
        *(float4*)&wv[4]  = *(const float4*)(wr + 4);
        *(float4*)&wv[8]  = *(const float4*)(wr + 8);
        *(float4*)&wv[12] = *(const float4*)(wr + 12);
        float a[4];
#pragma unroll
        for (int i = 0; i < 4; i++)
            a[i] = in_s[(m0 + i) * ld_in + kbase + kk];
#pragma unroll
        for (int i = 0; i < 4; i++) {
#pragma unroll
            for (int j = 0; j < 16; j++)
                acc[i][j] = fmaf(a[i], wv[j], acc[i][j]);
        }
    }
}

// ---------------------------------------------------------------------------
// GEMM: [64 x K] (smem) @ [K x 256] (global, streamed via smem double buffer)
// acc left in registers (4x16 per thread).
// ---------------------------------------------------------------------------
template <int K>
__device__ __forceinline__ void gemm(const float* __restrict__ Wg,
                                     const float* __restrict__ in_s, int ld_in,
                                     float* wbuf, float acc[4][16])
{
    const int tid = threadIdx.x;
    const int m0  = (tid >> 4) * 4;
    const int n0  = (tid & 15) * 16;

#pragma unroll
    for (int i = 0; i < 4; i++)
#pragma unroll
        for (int j = 0; j < 16; j++)
            acc[i][j] = 0.f;

    constexpr int NKT = K / 16;
    const float4* Wg4 = (const float4*)Wg;

    // preload k-tile 0 into buffer 0
    float4 r[4];
#pragma unroll
    for (int i = 0; i < 4; i++) r[i] = Wg4[tid + i * 256];
    {
        float4* wb4 = (float4*)wbuf;
#pragma unroll
        for (int i = 0; i < 4; i++) wb4[tid + i * 256] = r[i];
    }
    __syncthreads();   // also orders caller's smem-input writes

    for (int kt = 0; kt < NKT; kt++) {
        float* wcur = wbuf + (kt & 1) * 4096;
        if (kt + 1 < NKT) {
#pragma unroll
            for (int i = 0; i < 4; i++)
                r[i] = Wg4[(kt + 1) * 1024 + tid + i * 256];
        }
        mma_ktile(wcur, in_s, ld_in, kt * 16, m0, n0, acc);
        __syncthreads();                    // all reads of wcur done
        if (kt + 1 < NKT) {
            float4* wn4 = (float4*)(wbuf + ((kt + 1) & 1) * 4096);
#pragma unroll
            for (int i = 0; i < 4; i++) wn4[tid + i * 256] = r[i];
            __syncthreads();                // next tile visible
        }
    }
}

__device__ __forceinline__ void epilogue_relu(float acc[4][16],
                                              const float* __restrict__ bias,
                                              float* __restrict__ out_s)
{
    const int tid = threadIdx.x;
    const int m0  = (tid >> 4) * 4;
    const int n0  = (tid & 15) * 16;
    float bv[16];
#pragma unroll
    for (int j4 = 0; j4 < 4; j4++)
        *(float4*)&bv[j4 * 4] = *(const float4*)(bias + n0 + j4 * 4);
#pragma unroll
    for (int i = 0; i < 4; i++) {
#pragma unroll
        for (int j4 = 0; j4 < 4; j4++) {
            float4 v;
            v.x = fmaxf(acc[i][j4 * 4 + 0] + bv[j4 * 4 + 0], 0.f);
            v.y = fmaxf(acc[i][j4 * 4 + 1] + bv[j4 * 4 + 1], 0.f);
            v.z = fmaxf(acc[i][j4 * 4 + 2] + bv[j4 * 4 + 2], 0.f);
            v.w = fmaxf(acc[i][j4 * 4 + 3] + bv[j4 * 4 + 3], 0.f);
            *(float4*)&out_s[(m0 + i) * LDH + n0 + j4 * 4] = v;
        }
    }
}

// ---------------------------------------------------------------------------
// Kernel 1: fused phi MLP + masked partial pool per (batch, 64-row tile)
// ---------------------------------------------------------------------------
extern "C" __global__ void __launch_bounds__(256, 1)
phi_pool_kernel(const float* __restrict__ x, const int* __restrict__ mask,
                const float* __restrict__ pw1, const float* __restrict__ pb1,
                const float* __restrict__ pw2, const float* __restrict__ pb2,
                const float* __restrict__ pw3, const float* __restrict__ pb3)
{
    extern __shared__ float sm[];
    float* xS   = sm + OFF_XS;
    float* hA   = sm + OFF_HA;
    float* hB   = sm + OFF_HB;
    float* wbuf = sm + OFF_WB;

    const int tid     = threadIdx.x;
    const int tileIdx = blockIdx.x;
    const int b       = blockIdx.y;
    const int m0      = (tid >> 4) * 4;
    const int n0      = (tid & 15) * 16;

    // ---- load x tile [64 rows x 64 dims] ----
    const float4* xb4 = (const float4*)(x + ((size_t)(b * N_ + tileIdx * MT)) * DIN);
#pragma unroll
    for (int i = 0; i < 4; i++) {
        int idx = tid + i * 256;           // 1024 float4s total
        int row = idx >> 4;
        int c4  = idx & 15;
        *(float4*)&xS[row * LDX + c4 * 4] = xb4[idx];
    }
    // (gemm's preload __syncthreads orders these writes)

    float acc[4][16];

    // layer 1: 64 -> 256, relu
    gemm<DIN>(pw1, xS, LDX, wbuf, acc);
    epilogue_relu(acc, pb1, hA);

    // layer 2: 256 -> 256, relu
    gemm<HID>(pw2, hA, LDH, wbuf, acc);
    epilogue_relu(acc, pb2, hB);

    // layer 3: 256 -> 256, bias only, then masked pool
    gemm<HID>(pw3, hB, LDH, wbuf, acc);

    float bv[16];
#pragma unroll
    for (int j4 = 0; j4 < 4; j4++)
        *(float4*)&bv[j4 * 4] = *(const float4*)(pb3 + n0 + j4 * 4);

    const int* mb = mask + b * N_ + tileIdx * MT;
    float mv[4];
#pragma unroll
    for (int i = 0; i < 4; i++)
        mv[i] = (mb[m0 + i] != 0) ? 1.f : 0.f;

    float pacc[16];
#pragma unroll
    for (int j = 0; j < 16; j++) {
        float s = 0.f;
#pragma unroll
        for (int i = 0; i < 4; i++)
            s = fmaf(mv[i], acc[i][j] + bv[j], s);
        pacc[j] = s;
    }

    // reduce 16 m-groups -> [256]; reuse wbuf (all wbuf reads done: gemm ends with sync)
    float* red = wbuf;                      // [16][256]
    const int mg = tid >> 4;
#pragma unroll
    for (int j4 = 0; j4 < 4; j4++)
        *(float4*)&red[mg * 256 + n0 + j4 * 4] = *(float4*)&pacc[j4 * 4];
    __syncthreads();

    float s = 0.f;
#pragma unroll
    for (int g = 0; g < 16; g++)
        s += red[g * 256 + tid];
    g_partial[(b * TILES + tileIdx) * HID + tid] = s;
}

// ---------------------------------------------------------------------------
// Kernel 2: finish pool + rho MLP + valid-mask zeroing. One CTA per batch.
// ---------------------------------------------------------------------------
extern "C" __global__ void __launch_bounds__(256)
rho_kernel(const int* __restrict__ mask,
           const float* __restrict__ rw1, const float* __restrict__ rb1,
           const float* __restrict__ rw2, const float* __restrict__ rb2,
           const float* __restrict__ rw3, const float* __restrict__ rb3,
           float* __restrict__ out)
{
    const int b   = blockIdx.x;
    const int tid = threadIdx.x;
    __shared__ float p[HID];
    __shared__ float o1[HID];
    __shared__ int   anyv;

    if (tid == 0) anyv = 0;

    float s = 0.f;
#pragma unroll
    for (int t = 0; t < TILES; t++)
        s += g_partial[(b * TILES + t) * HID + tid];
    p[tid] = s;

    int v = 0;
    const int* mb = mask + b * N_;
#pragma unroll
    for (int i = 0; i < 4; i++)
        v |= mb[tid + i * 256];

    __syncthreads();              // p visible, anyv initialized
    if (v) atomicOr(&anyv, 1);

    // layer r1
    float a1 = rb1[tid];
#pragma unroll 8
    for (int k = 0; k < HID; k++)
        a1 = fmaf(p[k], rw1[k * HID + tid], a1);
    a1 = fmaxf(a1, 0.f);
    o1[tid] = a1;
    __syncthreads();              // o1 visible, all p reads done

    // layer r2 (result overwrites p)
    float a2 = rb2[tid];
#pragma unroll 8
    for (int k = 0; k < HID; k++)
        a2 = fmaf(o1[k], rw2[k * HID + tid], a2);
    a2 = fmaxf(a2, 0.f);
    p[tid] = a2;
    __syncthreads();              // o2 visible, anyv settled

    // layer r3: 256 -> 128
    if (tid < DOUT) {
        float a3 = rb3[tid];
#pragma unroll 8
        for (int k = 0; k < HID; k++)
            a3 = fmaf(p[k], rw3[k * DOUT + tid], a3);
        out[b * DOUT + tid] = anyv ? a3 : 0.f;
    }
}

// ---------------------------------------------------------------------------
extern "C" void kernel_launch(void* const* d_in, const int* in_sizes, int n_in,
                              void* d_out, int out_size)
{
    const float* x    = (const float*)d_in[0];
    const int*   mask = (const int*)  d_in[1];
    const float* pw1  = (const float*)d_in[2];
    const float* pb1  = (const float*)d_in[3];
    const float* pw2  = (const float*)d_in[4];
    const float* pb2  = (const float*)d_in[5];
    const float* pw3  = (const float*)d_in[6];
    const float* pb3  = (const float*)d_in[7];
    const float* rw1  = (const float*)d_in[8];
    const float* rb1  = (const float*)d_in[9];
    const float* rw2  = (const float*)d_in[10];
    const float* rb2  = (const float*)d_in[11];
    const float* rw3  = (const float*)d_in[12];
    const float* rb3  = (const float*)d_in[13];
    float* out = (float*)d_out;

    cudaFuncSetAttribute(phi_pool_kernel,
                         cudaFuncAttributeMaxDynamicSharedMemorySize, SMEM_BYTES);

    dim3 grid(TILES, B_);
    phi_pool_kernel<<<grid, 256, SMEM_BYTES>>>(x, mask, pw1, pb1, pw2, pb2, pw3, pb3);
    rho_kernel<<<B_, 256>>>(mask, rw1, rb1, rw2, rb2, rw3, rb3, out);
}

// round 2
// speedup vs baseline: 2.2799x; 2.2799x over previous
#include <cuda_runtime.h>

#define B_      256
#define N_      1024
#define DIN     64
#define HID     256
#define DOUT    128
#define MT      64           // rows per phi tile
#define TILES   (N_ / MT)    // 16
#define LDX     68           // padded row stride for x tile (floats)
#define LDH     260          // padded row stride for h tiles (floats)

// Dynamic smem layout (in floats):
//  xS  : [64][68]            = 4352
//  hA  : [64][260]           = 16640
//  hB  : [64][260]           = 16640
//  wbuf: [2][16][256]        = 8192   (also reused as 16x256 reduction buffer)
#define OFF_XS   0
#define OFF_HA   4352
#define OFF_HB   (4352 + 16640)
#define OFF_WB   (4352 + 16640 + 16640)
#define SMEM_FLOATS (OFF_WB + 8192)
#define SMEM_BYTES  (SMEM_FLOATS * 4)

// per-tile partial pooled sums: [B][TILES][HID]
__device__ float g_partial[B_ * TILES * HID];

typedef unsigned long long u64;

__device__ __forceinline__ u64 fma2(u64 a, u64 b, u64 c) {
    u64 d;
    asm("fma.rn.f32x2 %0, %1, %2, %3;" : "=l"(d) : "l"(a), "l"(b), "l"(c));
    return d;
}
__device__ __forceinline__ u64 pack2(float v) {
    u64 d;
    asm("mov.b64 %0, {%1, %1};" : "=l"(d) : "f"(v));
    return d;
}
__device__ __forceinline__ float2 unpack2(u64 v) {
    float2 r;
    asm("mov.b64 {%0, %1}, %2;" : "=f"(r.x), "=f"(r.y) : "l"(v));
    return r;
}

// ---------------------------------------------------------------------------
// inner MMA over one 16-row k-tile of W (in smem, [16][256] row-major).
// Thread tile: 4 rows (m0..m0+3) x 16 cols, cols = c0 + 64*g + {0..3}, g=0..3.
// acc[i][p]: p=2g   -> cols (c0+64g,   c0+64g+1)
//            p=2g+1 -> cols (c0+64g+2, c0+64g+3)
// Weight LDS.128 pattern: lane stride 16B -> conflict-free.
// ---------------------------------------------------------------------------
__device__ __forceinline__ void mma_ktile(const float* __restrict__ ws,   // [16][256]
                                          const float* __restrict__ in_s, // [64][ld]
                                          int ld_in, int kbase,
                                          int m0, int c0, u64 acc[4][8])
{
#pragma unroll
    for (int kk4 = 0; kk4 < 4; kk4++) {
        float4 av[4];
#pragma unroll
        for (int i = 0; i < 4; i++)
            av[i] = *(const float4*)&in_s[(m0 + i) * ld_in + kbase + kk4 * 4];
#pragma unroll
        for (int kkin = 0; kkin < 4; kkin++) {
            const float* wr = ws + (kk4 * 4 + kkin) * 256 + c0;
            ulonglong2 w01 = *(const ulonglong2*)(wr);
            ulonglong2 w23 = *(const ulonglong2*)(wr + 64);
            ulonglong2 w45 = *(const ulonglong2*)(wr + 128);
            ulonglong2 w67 = *(const ulonglong2*)(wr + 192);
            u64 wv[8] = { w01.x, w01.y, w23.x, w23.y, w45.x, w45.y, w67.x, w67.y };
#pragma unroll
            for (int i = 0; i < 4; i++) {
                float a = (kkin == 0) ? av[i].x : (kkin == 1) ? av[i].y
                         : (kkin == 2) ? av[i].z : av[i].w;
                u64 aa = pack2(a);
#pragma unroll
                for (int p = 0; p < 8; p++)
                    acc[i][p] = fma2(aa, wv[p], acc[i][p]);
            }
        }
    }
}

// ---------------------------------------------------------------------------
// GEMM: [64 x K] (smem) @ [K x 256] (global W, streamed via smem double buffer)
// Single __syncthreads per k-tile.
// ---------------------------------------------------------------------------
template <int K>
__device__ __forceinline__ void gemm(const float* __restrict__ Wg,
                                     const float* __restrict__ in_s, int ld_in,
                                     float* wbuf, u64 acc[4][8])
{
    const int tid = threadIdx.x;
    const int m0  = (tid >> 4) * 4;
    const int c0  = (tid & 15) * 4;

#pragma unroll
    for (int i = 0; i < 4; i++)
#pragma unroll
        for (int p = 0; p < 8; p++)
            acc[i][p] = 0ull;

    constexpr int NKT = K / 16;
    const float4* Wg4 = (const float4*)Wg;

    // preload k-tile 0 into buffer 0
    float4 r[4];
#pragma unroll
    for (int i = 0; i < 4; i++) r[i] = Wg4[tid + i * 256];
    {
        float4* wb4 = (float4*)wbuf;
#pragma unroll
        for (int i = 0; i < 4; i++) wb4[tid + i * 256] = r[i];
    }
    __syncthreads();   // also orders caller's smem-input writes

#pragma unroll
    for (int kt = 0; kt < NKT; kt++) {
        const float* wcur = wbuf + (kt & 1) * 4096;
        if (kt + 1 < NKT) {
#pragma unroll
            for (int i = 0; i < 4; i++)
                r[i] = Wg4[(kt + 1) * 1024 + tid + i * 256];
        }
        mma_ktile(wcur, in_s, ld_in, kt * 16, m0, c0, acc);
        if (kt + 1 < NKT) {
            float4* wn4 = (float4*)(wbuf + ((kt + 1) & 1) * 4096);
#pragma unroll
            for (int i = 0; i < 4; i++) wn4[tid + i * 256] = r[i];
        }
        __syncthreads();   // writes to other buffer visible; reads of wcur done
    }
}

__device__ __forceinline__ void epilogue_relu(u64 acc[4][8],
                                              const float* __restrict__ bias,
                                              float* __restrict__ out_s)
{
    const int tid = threadIdx.x;
    const int m0  = (tid >> 4) * 4;
    const int c0  = (tid & 15) * 4;
    float4 bv[4];
#pragma unroll
    for (int g = 0; g < 4; g++)
        bv[g] = *(const float4*)(bias + c0 + 64 * g);
#pragma unroll
    for (int i = 0; i < 4; i++) {
#pragma unroll
        for (int g = 0; g < 4; g++) {
            float2 u0 = unpack2(acc[i][2 * g]);
            float2 u1 = unpack2(acc[i][2 * g + 1]);
            float4 v;
            v.x = fmaxf(u0.x + bv[g].x, 0.f);
            v.y = fmaxf(u0.y + bv[g].y, 0.f);
            v.z = fmaxf(u1.x + bv[g].z, 0.f);
            v.w = fmaxf(u1.y + bv[g].w, 0.f);
            *(float4*)&out_s[(m0 + i) * LDH + c0 + 64 * g] = v;
        }
    }
}

// ---------------------------------------------------------------------------
// Kernel 1: fused phi MLP + masked partial pool per (batch, 64-row tile)
// ---------------------------------------------------------------------------
extern "C" __global__ void __launch_bounds__(256, 1)
phi_pool_kernel(const float* __restrict__ x, const int* __restrict__ mask,
                const float* __restrict__ pw1, const float* __restrict__ pb1,
                const float* __restrict__ pw2, const float* __restrict__ pb2,
                const float* __restrict__ pw3, const float* __restrict__ pb3)
{
    extern __shared__ float sm[];
    float* xS   = sm + OFF_XS;
    float* hA   = sm + OFF_HA;
    float* hB   = sm + OFF_HB;
    float* wbuf = sm + OFF_WB;

    const int tid     = threadIdx.x;
    const int tileIdx = blockIdx.x;
    const int b       = blockIdx.y;
    const int m0      = (tid >> 4) * 4;
    const int c0      = (tid & 15) * 4;
    const int mg      = tid >> 4;

    // ---- load x tile [64 rows x 64 dims] ----
    const float4* xb4 = (const float4*)(x + ((size_t)(b * N_ + tileIdx * MT)) * DIN);
#pragma unroll
    for (int i = 0; i < 4; i++) {
        int idx = tid + i * 256;           // 1024 float4s total
        int row = idx >> 4;
        int c4  = idx & 15;
        *(float4*)&xS[row * LDX + c4 * 4] = xb4[idx];
    }
    // (gemm's preload __syncthreads orders these writes)

    u64 acc[4][8];

    // layer 1: 64 -> 256, relu
    gemm<DIN>(pw1, xS, LDX, wbuf, acc);
    epilogue_relu(acc, pb1, hA);

    // layer 2: 256 -> 256, relu
    gemm<HID>(pw2, hA, LDH, wbuf, acc);
    epilogue_relu(acc, pb2, hB);

    // layer 3: 256 -> 256, bias only, then masked pool
    gemm<HID>(pw3, hB, LDH, wbuf, acc);

    float4 bv[4];
#pragma unroll
    for (int g = 0; g < 4; g++)
        bv[g] = *(const float4*)(pb3 + c0 + 64 * g);

    const int* mb = mask + b * N_ + tileIdx * MT;
    float mv[4];
#pragma unroll
    for (int i = 0; i < 4; i++)
        mv[i] = (mb[m0 + i] != 0) ? 1.f : 0.f;

    // masked partial pool over this thread's 4 rows -> 16 columns
    // reduce 16 m-groups -> [256]; reuse wbuf (gemm ends with a sync)
    float* red = wbuf;                      // [16][256]
#pragma unroll
    for (int g = 0; g < 4; g++) {
        float4 p4 = make_float4(0.f, 0.f, 0.f, 0.f);
#pragma unroll
        for (int i = 0; i < 4; i++) {
            float2 u0 = unpack2(acc[i][2 * g]);
            float2 u1 = unpack2(acc[i][2 * g + 1]);
            p4.x = fmaf(mv[i], u0.x + bv[g].x, p4.x);
            p4.y = fmaf(mv[i], u0.y + bv[g].y, p4.y);
            p4.z = fmaf(mv[i], u1.x + bv[g].z, p4.z);
            p4.w = fmaf(mv[i], u1.y + bv[g].w, p4.w);
        }
        *(float4*)&red[mg * 256 + c0 + 64 * g] = p4;
    }
    __syncthreads();

    float s = 0.f;
#pragma unroll
    for (int g = 0; g < 16; g++)
        s += red[g * 256 + tid];
    g_partial[(b * TILES + tileIdx) * HID + tid] = s;
}

// ---------------------------------------------------------------------------
// Kernel 2: finish pool + rho MLP + valid-mask zeroing. One CTA per batch.
// ---------------------------------------------------------------------------
extern "C" __global__ void __launch_bounds__(256)
rho_kernel(const int* __restrict__ mask,
           const float* __restrict__ rw1, const float* __restrict__ rb1,
           const float* __restrict__ rw2, const float* __restrict__ rb2,
           const float* __restrict__ rw3, const float* __restrict__ rb3,
           float* __restrict__ out)
{
    const int b   = blockIdx.x;
    const int tid = threadIdx.x;
    __shared__ float p[HID];
    __shared__ float o1[HID];
    __shared__ int   anyv;

    if (tid == 0) anyv = 0;

    float s = 0.f;
#pragma unroll
    for (int t = 0; t < TILES; t++)
        s += g_partial[(b * TILES + t) * HID + tid];
    p[tid] = s;

    int v = 0;
    const int* mb = mask + b * N_;
#pragma unroll
    for (int i = 0; i < 4; i++)
        v |= mb[tid + i * 256];

    __syncthreads();              // p visible, anyv initialized
    if (v) atomicOr(&anyv, 1);

    // layer r1
    float a1 = rb1[tid];
#pragma unroll 8
    for (int k = 0; k < HID; k++)
        a1 = fmaf(p[k], rw1[k * HID + tid], a1);
    a1 = fmaxf(a1, 0.f);
    o1[tid] = a1;
    __syncthreads();              // o1 visible, all p reads done

    // layer r2 (result overwrites p)
    float a2 = rb2[tid];
#pragma unroll 8
    for (int k = 0; k < HID; k++)
        a2 = fmaf(o1[k], rw2[k * HID + tid], a2);
    a2 = fmaxf(a2, 0.f);
    p[tid] = a2;
    __syncthreads();              // o2 visible, anyv settled

    // layer r3: 256 -> 128
    if (tid < DOUT) {
        float a3 = rb3[tid];
#pragma unroll 8
        for (int k = 0; k < HID; k++)
            a3 = fmaf(p[k], rw3[k * DOUT + tid], a3);
        out[b * DOUT + tid] = anyv ? a3 : 0.f;
    }
}

// ---------------------------------------------------------------------------
extern "C" void kernel_launch(void* const* d_in, const int* in_sizes, int n_in,
                              void* d_out, int out_size)
{
    const float* x    = (const float*)d_in[0];
    const int*   mask = (const int*)  d_in[1];
    const float* pw1  = (const float*)d_in[2];
    const float* pb1  = (const float*)d_in[3];
    const float* pw2  = (const float*)d_in[4];
    const float* pb2  = (const float*)d_in[5];
    const float* pw3  = (const float*)d_in[6];
    const float* pb3  = (const float*)d_in[7];
    const float* rw1  = (const float*)d_in[8];
    const float* rb1  = (const float*)d_in[9];
    const float* rw2  = (const float*)d_in[10];
    const float* rb2  = (const float*)d_in[11];
    const float* rw3  = (const float*)d_in[12];
    const float* rb3  = (const float*)d_in[13];
    float* out = (float*)d_out;

    cudaFuncSetAttribute(phi_pool_kernel,
                         cudaFuncAttributeMaxDynamicSharedMemorySize, SMEM_BYTES);

    dim3 grid(TILES, B_);
    phi_pool_kernel<<<grid, 256, SMEM_BYTES>>>(x, mask, pw1, pb1, pw2, pb2, pw3, pb3);
    rho_kernel<<<B_, 256>>>(mask, rw1, rb1, rw2, rb2, rw3, rb3, out);
}

// round 4
// speedup vs baseline: 4.5936x; 2.0149x over previous
#include <cuda_runtime.h>
#include <cuda_bf16.h>
#include <cstdint>

#define B_      256
#define N_      1024
#define DIN     64
#define HID     256
#define DOUT    128
#define MT      128
#define TILES   (N_ / MT)        // 8
#define THREADS 256
#define NCHUNKS 18               // 2 (K=64) + 8 + 8 chunks of k32

// smem layout (bytes)
#define SM_B     0                       // 2 buffers x 32768 (B chunk: [256 n][128B row: hi k32 | lo k32])
#define SM_BIAS  65536                   // 3 * 256 * 4
#define SM_POOL  68608                   // 8 * 256 * 4
#define SM_A     77824                   // A hi: [128 m][512B row] = 65536
#define SM_AL    (77824 + 65536)         // A lo
#define SM_BYTES (77824 + 131072)        // 208896

__device__ float g_partial[B_ * TILES * HID];
__device__ __align__(16) __nv_bfloat16 g_wt_hi[147456];
__device__ __align__(16) __nv_bfloat16 g_wt_lo[147456];
#define WT1 0
#define WT2 16384
#define WT3 81920

// ---------------------------------------------------------------------------
// helpers
// ---------------------------------------------------------------------------
__device__ __forceinline__ uint32_t smem_u32(const void* p) {
    uint32_t a;
    asm("{ .reg .u64 t; cvta.to.shared.u64 t, %1; cvt.u32.u64 %0, t; }"
        : "=r"(a) : "l"(p));
    return a;
}
__device__ __forceinline__ void ldm4(uint32_t r[4], uint32_t addr) {
    asm volatile("ldmatrix.sync.aligned.m8n8.x4.shared.b16 {%0,%1,%2,%3}, [%4];"
                 : "=r"(r[0]), "=r"(r[1]), "=r"(r[2]), "=r"(r[3]) : "r"(addr));
}
__device__ __forceinline__ void mma16816(float c[4], const uint32_t a[4],
                                         uint32_t b0, uint32_t b1) {
    asm volatile(
        "mma.sync.aligned.m16n8k16.row.col.f32.bf16.bf16.f32 "
        "{%0,%1,%2,%3}, {%4,%5,%6,%7}, {%8,%9}, {%0,%1,%2,%3};"
        : "+f"(c[0]), "+f"(c[1]), "+f"(c[2]), "+f"(c[3])
        : "r"(a[0]), "r"(a[1]), "r"(a[2]), "r"(a[3]), "r"(b0), "r"(b1));
}
__device__ __forceinline__ void cpasync16(uint32_t dst, const void* src) {
    asm volatile("cp.async.ca.shared.global [%0], [%1], 16;" :: "r"(dst), "l"(src));
}
#define CP_COMMIT() asm volatile("cp.async.commit_group;" ::: "memory")
#define CP_WAIT(N)  asm volatile("cp.async.wait_group %0;" :: "n"(N) : "memory")

// pack two fp32 -> bf16x2 (v0 -> low half / first element in memory)
__device__ __forceinline__ uint32_t cvt_bf2(float v0, float v1) {
    uint32_t r;
    asm("cvt.rn.bf16x2.f32 %0, %1, %2;" : "=r"(r) : "f"(v1), "f"(v0));
    return r;
}

// ---------------------------------------------------------------------------
// prep: transpose weights to [N][K], split fp32 -> bf16 hi/lo
// ---------------------------------------------------------------------------
extern "C" __global__ void prep_w(const float* __restrict__ pw1,
                                  const float* __restrict__ pw2,
                                  const float* __restrict__ pw3)
{
    int i = blockIdx.x * 256 + threadIdx.x;
    if (i >= 147456) return;
    float v; int dst;
    if (i < 16384) {            // pw1 [64][256] -> [256][64]
        int k = i >> 8, n = i & 255;
        v = pw1[i]; dst = WT1 + n * 64 + k;
    } else if (i < 81920) {     // pw2 [256][256]
        int j = i - 16384; int k = j >> 8, n = j & 255;
        v = pw2[j]; dst = WT2 + n * 256 + k;
    } else {                    // pw3 [256][256]
        int j = i - 81920; int k = j >> 8, n = j & 255;
        v = pw3[j]; dst = WT3 + n * 256 + k;
    }
    __nv_bfloat16 h = __float2bfloat16(v);
    g_wt_hi[dst] = h;
    g_wt_lo[dst] = __float2bfloat16(v - __bfloat162float(h));
}

// ---------------------------------------------------------------------------
// issue one B chunk (k32, hi+lo) via cp.async into buffer gi&1
// B smem row n (128B): chunks 0-3 = hi k0..31, 4-7 = lo; chunk c swizzled c^(n&7)
// ---------------------------------------------------------------------------
__device__ __forceinline__ void issue_chunk(int gi, uint32_t sb, int tid)
{
    const __nv_bfloat16 *hi, *lo; int K, kc;
    if (gi < 2)       { hi = g_wt_hi + WT1; lo = g_wt_lo + WT1; K = 64;  kc = gi; }
    else if (gi < 10) { hi = g_wt_hi + WT2; lo = g_wt_lo + WT2; K = 256; kc = gi - 2; }
    else              { hi = g_wt_hi + WT3; lo = g_wt_lo + WT3; K = 256; kc = gi - 10; }
    int n = tid;
    uint32_t dst = sb + SM_B + (uint32_t)(gi & 1) * 32768u + (uint32_t)n * 128u;
    const char* sh = (const char*)(hi + (size_t)n * K + kc * 32);
    const char* sl = (const char*)(lo + (size_t)n * K + kc * 32);
#pragma unroll
    for (int c = 0; c < 4; c++)
        cpasync16(dst + ((uint32_t)(c ^ (n & 7)) << 4), sh + c * 16);
#pragma unroll
    for (int c = 0; c < 4; c++)
        cpasync16(dst + ((uint32_t)((c + 4) ^ (n & 7)) << 4), sl + c * 16);
}

// epilogue pair store into A smem (hi+lo), swizzled
__device__ __forceinline__ void store_pair(char* smem, int row, int chunk, int t,
                                           float v0, float v1)
{
    uint32_t hi2 = cvt_bf2(v0, v1);
    float f0 = __uint_as_float(hi2 << 16);
    float f1 = __uint_as_float(hi2 & 0xffff0000u);
    uint32_t lo2 = cvt_bf2(v0 - f0, v1 - f1);
    uint32_t off = (uint32_t)row * 512u + ((uint32_t)(chunk ^ (row & 7)) << 4) + t * 4;
    *(uint32_t*)(smem + SM_A + off)  = hi2;
    *(uint32_t*)(smem + SM_AL + off) = lo2;
}

// ---------------------------------------------------------------------------
// phi kernel: 3-layer MLP on tensor cores (bf16 2-term split) + masked pool
// ---------------------------------------------------------------------------
extern "C" __global__ void __launch_bounds__(THREADS, 1)
phi_kernel(const float* __restrict__ x, const int* __restrict__ mask,
           const float* __restrict__ pb1, const float* __restrict__ pb2,
           const float* __restrict__ pb3)
{
    extern __shared__ char smem[];
    uint32_t sb = smem_u32(smem);
    const int tid = threadIdx.x, wid = tid >> 5, lane = tid & 31;
    const int tile = blockIdx.x, b = blockIdx.y;
    const int m0 = wid * 16, gg = lane >> 2, t = lane & 3;

    // biases -> smem
    ((float*)(smem + SM_BIAS))[tid]       = pb1[tid];
    ((float*)(smem + SM_BIAS))[256 + tid] = pb2[tid];
    ((float*)(smem + SM_BIAS))[512 + tid] = pb3[tid];

    // ---- x [128 rows][64] fp32 -> A smem bf16 hi/lo (chunks 0..7 of each row)
    {
        int row = tid >> 1, half = tid & 1;
        const float4* src = (const float4*)(x +
            ((size_t)(b * N_ + tile * MT + row)) * DIN + half * 32);
#pragma unroll
        for (int q = 0; q < 4; q++) {
            float4 a = src[q * 2], c = src[q * 2 + 1];
            float v[8] = { a.x, a.y, a.z, a.w, c.x, c.y, c.z, c.w };
            uint32_t hi[4], lo[4];
#pragma unroll
            for (int p = 0; p < 4; p++) {
                hi[p] = cvt_bf2(v[2 * p], v[2 * p + 1]);
                float f0 = __uint_as_float(hi[p] << 16);
                float f1 = __uint_as_float(hi[p] & 0xffff0000u);
                lo[p] = cvt_bf2(v[2 * p] - f0, v[2 * p + 1] - f1);
            }
            int kc = half * 4 + q;
            uint32_t off = (uint32_t)row * 512u + ((uint32_t)(kc ^ (row & 7)) << 4);
            *(uint4*)(smem + SM_A + off)  = make_uint4(hi[0], hi[1], hi[2], hi[3]);
            *(uint4*)(smem + SM_AL + off) = make_uint4(lo[0], lo[1], lo[2], lo[3]);
        }
    }

    // prefetch chunk 0
    issue_chunk(0, sb, tid);
    CP_COMMIT();
    __syncthreads();                     // x + biases visible

    float acc[32][4];
    int gi = 0;

    for (int l = 0; l < 3; l++) {
        const int nch = (l == 0) ? 2 : 8;
#pragma unroll
        for (int i = 0; i < 32; i++) {
            acc[i][0] = 0.f; acc[i][1] = 0.f; acc[i][2] = 0.f; acc[i][3] = 0.f;
        }
        for (int kc = 0; kc < nch; kc++) {
            if (gi + 1 < NCHUNKS) {
                issue_chunk(gi + 1, sb, tid);
                CP_COMMIT();
                CP_WAIT(1);
            } else {
                CP_WAIT(0);
            }
            __syncthreads();             // chunk gi ready in buf gi&1
            uint32_t bbase = sb + SM_B + (uint32_t)(gi & 1) * 32768u;
            uint32_t brow_ = (lane & 7) + ((lane >= 16) ? 8 : 0);
#pragma unroll
            for (int sc = 0; sc < 2; sc++) {
                int ks = kc * 2 + sc;
                // A fragments (hi, lo), m16k16 via ldmatrix.x4
                uint32_t arow = m0 + (lane & 15);
                uint32_t achk = 2 * ks + (lane >> 4);
                uint32_t aoff = arow * 512u + (((achk ^ (arow & 7))) << 4);
                uint32_t ah[4], al[4];
                ldm4(ah, sb + SM_A + aoff);
                ldm4(al, sb + SM_AL + aoff);

                uint32_t chi = 2 * sc + ((lane >> 3) & 1);
                uint32_t clo = chi + 4;

                // software-pipelined B fragments over 16 n16-tiles
                uint32_t bh[2][4], bl[2][4];
                {
                    uint32_t brow = brow_;
                    ldm4(bh[0], bbase + brow * 128u + ((chi ^ (brow & 7)) << 4));
                    ldm4(bl[0], bbase + brow * 128u + ((clo ^ (brow & 7)) << 4));
                }
#pragma unroll
                for (int nt = 0; nt < 16; nt++) {
                    int cur = nt & 1, nxt = cur ^ 1;
                    if (nt < 15) {
                        uint32_t brow = (nt + 1) * 16 + brow_;
                        ldm4(bh[nxt], bbase + brow * 128u + ((chi ^ (brow & 7)) << 4));
                        ldm4(bl[nxt], bbase + brow * 128u + ((clo ^ (brow & 7)) << 4));
                    }
                    mma16816(acc[2 * nt],     ah, bh[cur][0], bh[cur][1]);
                    mma16816(acc[2 * nt],     ah, bl[cur][0], bl[cur][1]);
                    mma16816(acc[2 * nt],     al, bh[cur][0], bh[cur][1]);
                    mma16816(acc[2 * nt + 1], ah, bh[cur][2], bh[cur][3]);
                    mma16816(acc[2 * nt + 1], ah, bl[cur][2], bl[cur][3]);
                    mma16816(acc[2 * nt + 1], al, bh[cur][2], bh[cur][3]);
                }
            }
            __syncthreads();             // compute done before buf reuse
            gi++;
        }

        if (l < 2) {
            // epilogue: bias + relu + split -> A smem (own rows only)
            const float* bias = (const float*)(smem + SM_BIAS) + l * 256;
            int r0 = m0 + gg, r1 = r0 + 8;
#pragma unroll
            for (int nt = 0; nt < 16; nt++) {
                int n0 = nt * 16;
                float b0 = bias[n0 + 2 * t],     b1 = bias[n0 + 2 * t + 1];
                float b2 = bias[n0 + 8 + 2 * t], b3 = bias[n0 + 8 + 2 * t + 1];
                store_pair(smem, r0, 2 * nt, t,
                           fmaxf(acc[2 * nt][0] + b0, 0.f),
                           fmaxf(acc[2 * nt][1] + b1, 0.f));
                store_pair(smem, r1, 2 * nt, t,
                           fmaxf(acc[2 * nt][2] + b0, 0.f),
                           fmaxf(acc[2 * nt][3] + b1, 0.f));
                store_pair(smem, r0, 2 * nt + 1, t,
                           fmaxf(acc[2 * nt + 1][0] + b2, 0.f),
                           fmaxf(acc[2 * nt + 1][1] + b3, 0.f));
                store_pair(smem, r1, 2 * nt + 1, t,
                           fmaxf(acc[2 * nt + 1][2] + b2, 0.f),
                           fmaxf(acc[2 * nt + 1][3] + b3, 0.f));
            }
            __syncwarp();                // next layer's ldmatrix reads these
        } else {
            // masked pool: bias + mask-weight + reduce over rows
            const float* bias = (const float*)(smem + SM_BIAS) + 512;
            int r0 = m0 + gg, r1 = r0 + 8;
            const int* mrow = mask + b * N_ + tile * MT;
            float mv0 = mrow[r0] ? 1.f : 0.f;
            float mv1 = mrow[r1] ? 1.f : 0.f;
            float* pool = (float*)(smem + SM_POOL) + wid * 256;
#pragma unroll
            for (int nt = 0; nt < 16; nt++) {
                int n0 = nt * 16;
                float b0 = bias[n0 + 2 * t],     b1 = bias[n0 + 2 * t + 1];
                float b2 = bias[n0 + 8 + 2 * t], b3 = bias[n0 + 8 + 2 * t + 1];
                float s0 = mv0 * (acc[2 * nt][0] + b0) + mv1 * (acc[2 * nt][2] + b0);
                float s1 = mv0 * (acc[2 * nt][1] + b1) + mv1 * (acc[2 * nt][3] + b1);
                float s2 = mv0 * (acc[2 * nt + 1][0] + b2) + mv1 * (acc[2 * nt + 1][2] + b2);
                float s3 = mv0 * (acc[2 * nt + 1][1] + b3) + mv1 * (acc[2 * nt + 1][3] + b3);
#pragma unroll
                for (int d = 4; d < 32; d <<= 1) {
                    s0 += __shfl_xor_sync(0xffffffff, s0, d);
                    s1 += __shfl_xor_sync(0xffffffff, s1, d);
                    s2 += __shfl_xor_sync(0xffffffff, s2, d);
                    s3 += __shfl_xor_sync(0xffffffff, s3, d);
                }
                if (lane < 4) {
                    pool[n0 + 2 * t]     = s0;
                    pool[n0 + 2 * t + 1] = s1;
                    pool[n0 + 8 + 2 * t]     = s2;
                    pool[n0 + 8 + 2 * t + 1] = s3;
                }
            }
            __syncthreads();
            float s = 0.f;
#pragma unroll
            for (int w = 0; w < 8; w++)
                s += ((const float*)(smem + SM_POOL))[w * 256 + tid];
            g_partial[(b * TILES + tile) * HID + tid] = s;
        }
    }
}

// ---------------------------------------------------------------------------
// rho kernel: finish pool + 3-layer MLP + valid zeroing. One CTA per batch.
// ---------------------------------------------------------------------------
extern "C" __global__ void __launch_bounds__(256)
rho_kernel(const int* __restrict__ mask,
           const float* __restrict__ rw1, const float* __restrict__ rb1,
           const float* __restrict__ rw2, const float* __restrict__ rb2,
           const float* __restrict__ rw3, const float* __restrict__ rb3,
           float* __restrict__ out)
{
    const int b   = blockIdx.x;
    const int tid = threadIdx.x;
    __shared__ float p[HID];
    __shared__ float o1[HID];
    __shared__ int   anyv;

    if (tid == 0) anyv = 0;

    float s = 0.f;
#pragma unroll
    for (int t = 0; t < TILES; t++)
        s += g_partial[(b * TILES + t) * HID + tid];
    p[tid] = s;

    int v = 0;
    const int* mb = mask + b * N_;
#pragma unroll
    for (int i = 0; i < 4; i++)
        v |= mb[tid + i * 256];

    __syncthreads();
    if (v) atomicOr(&anyv, 1);

    float a1 = rb1[tid];
#pragma unroll 8
    for (int k = 0; k < HID; k++)
        a1 = fmaf(p[k], rw1[k * HID + tid], a1);
    a1 = fmaxf(a1, 0.f);
    o1[tid] = a1;
    __syncthreads();

    float a2 = rb2[tid];
#pragma unroll 8
    for (int k = 0; k < HID; k++)
        a2 = fmaf(o1[k], rw2[k * HID + tid], a2);
    a2 = fmaxf(a2, 0.f);
    p[tid] = a2;
    __syncthreads();

    if (tid < DOUT) {
        float a3 = rb3[tid];
#pragma unroll 8
        for (int k = 0; k < HID; k++)
            a3 = fmaf(p[k], rw3[k * DOUT + tid], a3);
        out[b * DOUT + tid] = anyv ? a3 : 0.f;
    }
}

// ---------------------------------------------------------------------------
extern "C" void kernel_launch(void* const* d_in, const int* in_sizes, int n_in,
                              void* d_out, int out_size)
{
    const float* x    = (const float*)d_in[0];
    const int*   mask = (const int*)  d_in[1];
    const float* pw1  = (const float*)d_in[2];
    const float* pb1  = (const float*)d_in[3];
    const float* pw2  = (const float*)d_in[4];
    const float* pb2  = (const float*)d_in[5];
    const float* pw3  = (const float*)d_in[6];
    const float* pb3  = (const float*)d_in[7];
    const float* rw1  = (const float*)d_in[8];
    const float* rb1  = (const float*)d_in[9];
    const float* rw2  = (const float*)d_in[10];
    const float* rb2  = (const float*)d_in[11];
    const float* rw3  = (const float*)d_in[12];
    const float* rb3  = (const float*)d_in[13];
    float* out = (float*)d_out;

    cudaFuncSetAttribute(phi_kernel,
                         cudaFuncAttributeMaxDynamicSharedMemorySize, SM_BYTES);

    prep_w<<<576, 256>>>(pw1, pw2, pw3);
    dim3 grid(TILES, B_);
    phi_kernel<<<grid, THREADS, SM_BYTES>>>(x, mask, pb1, pb2, pb3);
    rho_kernel<<<B_, 256>>>(mask, rw1, rb1, rw2, rb2, rw3, rb3, out);
}

// round 5
// speedup vs baseline: 7.8942x; 1.7185x over previous
#include <cuda_runtime.h>
#include <cuda_bf16.h>
#include <cstdint>

#define B_      256
#define N_      1024
#define DIN     64
#define HID     256
#define DOUT    128
#define MT      128
#define TILES   (N_ / MT)        // 8 (max tiles per batch)
#define THREADS 256
#define NCHUNKS 18               // 2 (K=64) + 8 + 8 chunks of k32

// smem layout (bytes)
#define SM_B     0                       // 2 buffers x 32768
#define SM_BIAS  65536                   // 3 * 256 * 4
#define SM_POOL  68608                   // 8 * 256 * 4
#define SM_A     77824                   // A hi: [128 m][512B row]
#define SM_AL    (77824 + 65536)         // A lo
#define SM_BYTES (77824 + 131072)        // 208896

__device__ float g_partial[B_ * TILES * HID];
__device__ __align__(16) __nv_bfloat16 g_wt_hi[147456];
__device__ __align__(16) __nv_bfloat16 g_wt_lo[147456];
__device__ int g_cnt[B_];
__device__ int g_idx[B_ * N_];
#define WT1 0
#define WT2 16384
#define WT3 81920

// ---------------------------------------------------------------------------
// helpers
// ---------------------------------------------------------------------------
__device__ __forceinline__ uint32_t smem_u32(const void* p) {
    uint32_t a;
    asm("{ .reg .u64 t; cvta.to.shared.u64 t, %1; cvt.u32.u64 %0, t; }"
        : "=r"(a) : "l"(p));
    return a;
}
__device__ __forceinline__ void ldm4(uint32_t r[4], uint32_t addr) {
    asm volatile("ldmatrix.sync.aligned.m8n8.x4.shared.b16 {%0,%1,%2,%3}, [%4];"
                 : "=r"(r[0]), "=r"(r[1]), "=r"(r[2]), "=r"(r[3]) : "r"(addr));
}
__device__ __forceinline__ void mma16816(float c[4], const uint32_t a[4],
                                         uint32_t b0, uint32_t b1) {
    asm volatile(
        "mma.sync.aligned.m16n8k16.row.col.f32.bf16.bf16.f32 "
        "{%0,%1,%2,%3}, {%4,%5,%6,%7}, {%8,%9}, {%0,%1,%2,%3};"
        : "+f"(c[0]), "+f"(c[1]), "+f"(c[2]), "+f"(c[3])
        : "r"(a[0]), "r"(a[1]), "r"(a[2]), "r"(a[3]), "r"(b0), "r"(b1));
}
__device__ __forceinline__ void cpasync16(uint32_t dst, const void* src) {
    asm volatile("cp.async.ca.shared.global [%0], [%1], 16;" :: "r"(dst), "l"(src));
}
#define CP_COMMIT() asm volatile("cp.async.commit_group;" ::: "memory")
#define CP_WAIT(N)  asm volatile("cp.async.wait_group %0;" :: "n"(N) : "memory")

__device__ __forceinline__ uint32_t cvt_bf2(float v0, float v1) {
    uint32_t r;
    asm("cvt.rn.bf16x2.f32 %0, %1, %2;" : "=r"(r) : "f"(v1), "f"(v0));
    return r;
}

// ---------------------------------------------------------------------------
// prep_w: transpose weights to [N][K], split fp32 -> bf16 hi/lo
// ---------------------------------------------------------------------------
extern "C" __global__ void prep_w(const float* __restrict__ pw1,
                                  const float* __restrict__ pw2,
                                  const float* __restrict__ pw3)
{
    int i = blockIdx.x * 256 + threadIdx.x;
    if (i >= 147456) return;
    float v; int dst;
    if (i < 16384) {            // pw1 [64][256] -> [256][64]
        int k = i >> 8, n = i & 255;
        v = pw1[i]; dst = WT1 + n * 64 + k;
    } else if (i < 81920) {     // pw2 [256][256]
        int j = i - 16384; int k = j >> 8, n = j & 255;
        v = pw2[j]; dst = WT2 + n * 256 + k;
    } else {                    // pw3 [256][256]
        int j = i - 81920; int k = j >> 8, n = j & 255;
        v = pw3[j]; dst = WT3 + n * 256 + k;
    }
    __nv_bfloat16 h = __float2bfloat16(v);
    g_wt_hi[dst] = h;
    g_wt_lo[dst] = __float2bfloat16(v - __bfloat162float(h));
}

// ---------------------------------------------------------------------------
// prep_idx: per-batch compaction of valid row indices (order-preserving)
// ---------------------------------------------------------------------------
extern "C" __global__ void __launch_bounds__(256)
prep_idx(const int* __restrict__ mask)
{
    const int b = blockIdx.x, tid = threadIdx.x;
    const int lane = tid & 31, wid = tid >> 5;
    const int* mb = mask + b * N_;
    int v[4]; int c = 0;
#pragma unroll
    for (int i = 0; i < 4; i++) { v[i] = (mb[tid * 4 + i] != 0); c += v[i]; }
    // inclusive warp scan of c
    int pre = c;
#pragma unroll
    for (int d = 1; d < 32; d <<= 1) {
        int t = __shfl_up_sync(0xffffffffu, pre, d);
        if (lane >= d) pre += t;
    }
    __shared__ int wsum[8];
    if (lane == 31) wsum[wid] = pre;
    __syncthreads();
    int wbase = 0;
#pragma unroll
    for (int w = 0; w < 8; w++)
        if (w < wid) wbase += wsum[w];
    int o = wbase + pre - c;     // exclusive prefix for this thread
#pragma unroll
    for (int i = 0; i < 4; i++)
        if (v[i]) g_idx[b * N_ + (o++)] = tid * 4 + i;
    if (tid == 255) g_cnt[b] = wbase + pre;
}

// ---------------------------------------------------------------------------
// issue one B chunk (k32, hi+lo) via cp.async into buffer gi&1
// ---------------------------------------------------------------------------
__device__ __forceinline__ void issue_chunk(int gi, uint32_t sb, int tid)
{
    const __nv_bfloat16 *hi, *lo; int K, kc;
    if (gi < 2)       { hi = g_wt_hi + WT1; lo = g_wt_lo + WT1; K = 64;  kc = gi; }
    else if (gi < 10) { hi = g_wt_hi + WT2; lo = g_wt_lo + WT2; K = 256; kc = gi - 2; }
    else              { hi = g_wt_hi + WT3; lo = g_wt_lo + WT3; K = 256; kc = gi - 10; }
    int n = tid;
    uint32_t dst = sb + SM_B + (uint32_t)(gi & 1) * 32768u + (uint32_t)n * 128u;
    const char* sh = (const char*)(hi + (size_t)n * K + kc * 32);
    const char* sl = (const char*)(lo + (size_t)n * K + kc * 32);
#pragma unroll
    for (int c = 0; c < 4; c++)
        cpasync16(dst + ((uint32_t)(c ^ (n & 7)) << 4), sh + c * 16);
#pragma unroll
    for (int c = 0; c < 4; c++)
        cpasync16(dst + ((uint32_t)((c + 4) ^ (n & 7)) << 4), sl + c * 16);
}

// epilogue pair store into A smem (hi+lo), swizzled
__device__ __forceinline__ void store_pair(char* smem, int row, int chunk, int t,
                                           float v0, float v1)
{
    uint32_t hi2 = cvt_bf2(v0, v1);
    float f0 = __uint_as_float(hi2 << 16);
    float f1 = __uint_as_float(hi2 & 0xffff0000u);
    uint32_t lo2 = cvt_bf2(v0 - f0, v1 - f1);
    uint32_t off = (uint32_t)row * 512u + ((uint32_t)(chunk ^ (row & 7)) << 4) + t * 4;
    *(uint32_t*)(smem + SM_A + off)  = hi2;
    *(uint32_t*)(smem + SM_AL + off) = lo2;
}

// ---------------------------------------------------------------------------
// phi kernel: gathered valid rows only; 3-layer MLP (bf16 2-term split) + pool
// ---------------------------------------------------------------------------
extern "C" __global__ void __launch_bounds__(THREADS, 1)
phi_kernel(const float* __restrict__ x,
           const float* __restrict__ pb1, const float* __restrict__ pb2,
           const float* __restrict__ pb3)
{
    const int tile = blockIdx.x, b = blockIdx.y;
    const int cnt = g_cnt[b];
    if (tile * MT >= cnt) return;          // nothing to do for this tile

    extern __shared__ char smem[];
    uint32_t sb = smem_u32(smem);
    const int tid = threadIdx.x, wid = tid >> 5, lane = tid & 31;
    const int m0 = wid * 16, gg = lane >> 2, t = lane & 3;

    // biases -> smem
    ((float*)(smem + SM_BIAS))[tid]       = pb1[tid];
    ((float*)(smem + SM_BIAS))[256 + tid] = pb2[tid];
    ((float*)(smem + SM_BIAS))[512 + tid] = pb3[tid];

    // ---- gather x rows (compacted) -> A smem bf16 hi/lo; zero padding slots
    {
        int row = tid >> 1, half = tid & 1;
        int slot = tile * MT + row;
        bool vld = slot < cnt;
        int r = vld ? g_idx[b * N_ + slot] : 0;
        const float4* src = (const float4*)(x +
            ((size_t)(b * N_ + r)) * DIN + half * 32);
#pragma unroll
        for (int q = 0; q < 4; q++) {
            int kc = half * 4 + q;
            uint32_t off = (uint32_t)row * 512u + ((uint32_t)(kc ^ (row & 7)) << 4);
            if (vld) {
                float4 a = src[q * 2], c = src[q * 2 + 1];
                float v[8] = { a.x, a.y, a.z, a.w, c.x, c.y, c.z, c.w };
                uint32_t hi[4], lo[4];
#pragma unroll
                for (int p = 0; p < 4; p++) {
                    hi[p] = cvt_bf2(v[2 * p], v[2 * p + 1]);
                    float f0 = __uint_as_float(hi[p] << 16);
                    float f1 = __uint_as_float(hi[p] & 0xffff0000u);
                    lo[p] = cvt_bf2(v[2 * p] - f0, v[2 * p + 1] - f1);
                }
                *(uint4*)(smem + SM_A + off)  = make_uint4(hi[0], hi[1], hi[2], hi[3]);
                *(uint4*)(smem + SM_AL + off) = make_uint4(lo[0], lo[1], lo[2], lo[3]);
            } else {
                *(uint4*)(smem + SM_A + off)  = make_uint4(0, 0, 0, 0);
                *(uint4*)(smem + SM_AL + off) = make_uint4(0, 0, 0, 0);
            }
        }
    }

    // prefetch chunk 0
    issue_chunk(0, sb, tid);
    CP_COMMIT();
    __syncthreads();                     // x + biases visible

    float acc[32][4];
    int gi = 0;

    for (int l = 0; l < 3; l++) {
        const int nch = (l == 0) ? 2 : 8;
#pragma unroll
        for (int i = 0; i < 32; i++) {
            acc[i][0] = 0.f; acc[i][1] = 0.f; acc[i][2] = 0.f; acc[i][3] = 0.f;
        }
        for (int kc = 0; kc < nch; kc++) {
            if (gi + 1 < NCHUNKS) {
                issue_chunk(gi + 1, sb, tid);
                CP_COMMIT();
                CP_WAIT(1);
            } else {
                CP_WAIT(0);
            }
            __syncthreads();             // chunk gi ready in buf gi&1
            uint32_t bbase = sb + SM_B + (uint32_t)(gi & 1) * 32768u;
            uint32_t brow_ = (lane & 7) + ((lane >= 16) ? 8 : 0);
#pragma unroll
            for (int sc = 0; sc < 2; sc++) {
                int ks = kc * 2 + sc;
                uint32_t arow = m0 + (lane & 15);
                uint32_t achk = 2 * ks + (lane >> 4);
                uint32_t aoff = arow * 512u + (((achk ^ (arow & 7))) << 4);
                uint32_t ah[4], al[4];
                ldm4(ah, sb + SM_A + aoff);
                ldm4(al, sb + SM_AL + aoff);

                uint32_t chi = 2 * sc + ((lane >> 3) & 1);
                uint32_t clo = chi + 4;

                uint32_t bh[2][4], bl[2][4];
                {
                    uint32_t brow = brow_;
                    ldm4(bh[0], bbase + brow * 128u + ((chi ^ (brow & 7)) << 4));
                    ldm4(bl[0], bbase + brow * 128u + ((clo ^ (brow & 7)) << 4));
                }
#pragma unroll
                for (int nt = 0; nt < 16; nt++) {
                    int cur = nt & 1, nxt = cur ^ 1;
                    if (nt < 15) {
                        uint32_t brow = (nt + 1) * 16 + brow_;
                        ldm4(bh[nxt], bbase + brow * 128u + ((chi ^ (brow & 7)) << 4));
                        ldm4(bl[nxt], bbase + brow * 128u + ((clo ^ (brow & 7)) << 4));
                    }
                    mma16816(acc[2 * nt],     ah, bh[cur][0], bh[cur][1]);
                    mma16816(acc[2 * nt],     ah, bl[cur][0], bl[cur][1]);
                    mma16816(acc[2 * nt],     al, bh[cur][0], bh[cur][1]);
                    mma16816(acc[2 * nt + 1], ah, bh[cur][2], bh[cur][3]);
                    mma16816(acc[2 * nt + 1], ah, bl[cur][2], bl[cur][3]);
                    mma16816(acc[2 * nt + 1], al, bh[cur][2], bh[cur][3]);
                }
            }
            __syncthreads();             // compute done before buf reuse
            gi++;
        }

        if (l < 2) {
            const float* bias = (const float*)(smem + SM_BIAS) + l * 256;
            int r0 = m0 + gg, r1 = r0 + 8;
#pragma unroll
            for (int nt = 0; nt < 16; nt++) {
                int n0 = nt * 16;
                float b0 = bias[n0 + 2 * t],     b1 = bias[n0 + 2 * t + 1];
                float b2 = bias[n0 + 8 + 2 * t], b3 = bias[n0 + 8 + 2 * t + 1];
                store_pair(smem, r0, 2 * nt, t,
                           fmaxf(acc[2 * nt][0] + b0, 0.f),
                           fmaxf(acc[2 * nt][1] + b1, 0.f));
                store_pair(smem, r1, 2 * nt, t,
                           fmaxf(acc[2 * nt][2] + b0, 0.f),
                           fmaxf(acc[2 * nt][3] + b1, 0.f));
                store_pair(smem, r0, 2 * nt + 1, t,
                           fmaxf(acc[2 * nt + 1][0] + b2, 0.f),
                           fmaxf(acc[2 * nt + 1][1] + b3, 0.f));
                store_pair(smem, r1, 2 * nt + 1, t,
                           fmaxf(acc[2 * nt + 1][2] + b2, 0.f),
                           fmaxf(acc[2 * nt + 1][3] + b3, 0.f));
            }
            __syncwarp();
        } else {
            // masked pool: slot validity is the mask (all gathered rows valid)
            const float* bias = (const float*)(smem + SM_BIAS) + 512;
            int r0 = m0 + gg, r1 = r0 + 8;
            float mv0 = (tile * MT + r0 < cnt) ? 1.f : 0.f;
            float mv1 = (tile * MT + r1 < cnt) ? 1.f : 0.f;
            float* pool = (float*)(smem + SM_POOL) + wid * 256;
#pragma unroll
            for (int nt = 0; nt < 16; nt++) {
                int n0 = nt * 16;
                float b0 = bias[n0 + 2 * t],     b1 = bias[n0 + 2 * t + 1];
                float b2 = bias[n0 + 8 + 2 * t], b3 = bias[n0 + 8 + 2 * t + 1];
                float s0 = mv0 * (acc[2 * nt][0] + b0) + mv1 * (acc[2 * nt][2] + b0);
                float s1 = mv0 * (acc[2 * nt][1] + b1) + mv1 * (acc[2 * nt][3] + b1);
                float s2 = mv0 * (acc[2 * nt + 1][0] + b2) + mv1 * (acc[2 * nt + 1][2] + b2);
                float s3 = mv0 * (acc[2 * nt + 1][1] + b3) + mv1 * (acc[2 * nt + 1][3] + b3);
#pragma unroll
                for (int d = 4; d < 32; d <<= 1) {
                    s0 += __shfl_xor_sync(0xffffffff, s0, d);
                    s1 += __shfl_xor_sync(0xffffffff, s1, d);
                    s2 += __shfl_xor_sync(0xffffffff, s2, d);
                    s3 += __shfl_xor_sync(0xffffffff, s3, d);
                }
                if (lane < 4) {
                    pool[n0 + 2 * t]         = s0;
                    pool[n0 + 2 * t + 1]     = s1;
                    pool[n0 + 8 + 2 * t]     = s2;
                    pool[n0 + 8 + 2 * t + 1] = s3;
                }
            }
            __syncthreads();
            float s = 0.f;
#pragma unroll
            for (int w = 0; w < 8; w++)
                s += ((const float*)(smem + SM_POOL))[w * 256 + tid];
            g_partial[(b * TILES + tile) * HID + tid] = s;
        }
    }
}

// ---------------------------------------------------------------------------
// rho kernel: finish pool (only live tiles) + 3-layer MLP + zeroing
// ---------------------------------------------------------------------------
extern "C" __global__ void __launch_bounds__(256)
rho_kernel(const float* __restrict__ rw1, const float* __restrict__ rb1,
           const float* __restrict__ rw2, const float* __restrict__ rb2,
           const float* __restrict__ rw3, const float* __restrict__ rb3,
           float* __restrict__ out)
{
    const int b   = blockIdx.x;
    const int tid = threadIdx.x;
    __shared__ float p[HID];
    __shared__ float o1[HID];

    const int cnt = g_cnt[b];
    const int nt  = (cnt + MT - 1) / MT;

    float s = 0.f;
    for (int t = 0; t < nt; t++)
        s += g_partial[(b * TILES + t) * HID + tid];
    p[tid] = s;
    __syncthreads();

    float a1 = rb1[tid];
#pragma unroll 16
    for (int k = 0; k < HID; k++)
        a1 = fmaf(p[k], rw1[k * HID + tid], a1);
    a1 = fmaxf(a1, 0.f);
    o1[tid] = a1;
    __syncthreads();

    float a2 = rb2[tid];
#pragma unroll 16
    for (int k = 0; k < HID; k++)
        a2 = fmaf(o1[k], rw2[k * HID + tid], a2);
    a2 = fmaxf(a2, 0.f);
    p[tid] = a2;
    __syncthreads();

    if (tid < DOUT) {
        float a3 = rb3[tid];
#pragma unroll 16
        for (int k = 0; k < HID; k++)
            a3 = fmaf(p[k], rw3[k * DOUT + tid], a3);
        out[b * DOUT + tid] = (cnt > 0) ? a3 : 0.f;
    }
}

// ---------------------------------------------------------------------------
extern "C" void kernel_launch(void* const* d_in, const int* in_sizes, int n_in,
                              void* d_out, int out_size)
{
    const float* x    = (const float*)d_in[0];
    const int*   mask = (const int*)  d_in[1];
    const float* pw1  = (const float*)d_in[2];
    const float* pb1  = (const float*)d_in[3];
    const float* pw2  = (const float*)d_in[4];
    const float* pb2  = (const float*)d_in[5];
    const float* pw3  = (const float*)d_in[6];
    const float* pb3  = (const float*)d_in[7];
    const float* rw1  = (const float*)d_in[8];
    const float* rb1  = (const float*)d_in[9];
    const float* rw2  = (const float*)d_in[10];
    const float* rb2  = (const float*)d_in[11];
    const float* rw3  = (const float*)d_in[12];
    const float* rb3  = (const float*)d_in[13];
    float* out = (float*)d_out;

    cudaFuncSetAttribute(phi_kernel,
                         cudaFuncAttributeMaxDynamicSharedMemorySize, SM_BYTES);

    prep_w<<<576, 256>>>(pw1, pw2, pw3);
    prep_idx<<<B_, 256>>>(mask);
    dim3 grid(TILES, B_);
    phi_kernel<<<grid, THREADS, SM_BYTES>>>(x, pb1, pb2, pb3);
    rho_kernel<<<B_, 256>>>(rw1, rb1, rw2, rb2, rw3, rb3, out);
}

// round 6
// speedup vs baseline: 10.1576x; 1.2867x over previous
#include <cuda_runtime.h>
#include <cuda_fp16.h>
#include <cstdint>

#define B_      256
#define N_      1024
#define DIN     64
#define HID     256
#define DOUT    128
#define MT      128
#define TILES   (N_ / MT)        // 8 (max tiles per batch)
#define THREADS 256
#define NCHUNKS 18               // 2 (K=64) + 8 + 8 chunks of k32

// smem layout (bytes)
#define SM_B     0                       // 2 buffers x 32768 (B: [256 n][128B: Wh k32 | Wl k32])
#define SM_BIAS  65536                   // 3 * 256 * 4
#define SM_POOL  68608                   // 8 * 256 * 4
#define SM_A     77824                   // A fp16: [128 m][512B row]
#define SM_BYTES (77824 + 65536)         // 143360

__device__ float g_partial[B_ * TILES * HID];
__device__ __align__(16) __half g_wt_hi[147456];
__device__ __align__(16) __half g_wt_lo[147456];
__device__ int g_cnt[B_];
__device__ int g_idx[B_ * N_];
#define WT1 0
#define WT2 16384
#define WT3 81920

// ---------------------------------------------------------------------------
// helpers
// ---------------------------------------------------------------------------
__device__ __forceinline__ uint32_t smem_u32(const void* p) {
    uint32_t a;
    asm("{ .reg .u64 t; cvta.to.shared.u64 t, %1; cvt.u32.u64 %0, t; }"
        : "=r"(a) : "l"(p));
    return a;
}
__device__ __forceinline__ void ldm4(uint32_t r[4], uint32_t addr) {
    asm volatile("ldmatrix.sync.aligned.m8n8.x4.shared.b16 {%0,%1,%2,%3}, [%4];"
                 : "=r"(r[0]), "=r"(r[1]), "=r"(r[2]), "=r"(r[3]) : "r"(addr));
}
__device__ __forceinline__ void mma16816(float c[4], const uint32_t a[4],
                                         uint32_t b0, uint32_t b1) {
    asm volatile(
        "mma.sync.aligned.m16n8k16.row.col.f32.f16.f16.f32 "
        "{%0,%1,%2,%3}, {%4,%5,%6,%7}, {%8,%9}, {%0,%1,%2,%3};"
        : "+f"(c[0]), "+f"(c[1]), "+f"(c[2]), "+f"(c[3])
        : "r"(a[0]), "r"(a[1]), "r"(a[2]), "r"(a[3]), "r"(b0), "r"(b1));
}
__device__ __forceinline__ void cpasync16(uint32_t dst, const void* src) {
    asm volatile("cp.async.ca.shared.global [%0], [%1], 16;" :: "r"(dst), "l"(src));
}
#define CP_COMMIT() asm volatile("cp.async.commit_group;" ::: "memory")
#define CP_WAIT(N)  asm volatile("cp.async.wait_group %0;" :: "n"(N) : "memory")

// pack two fp32 -> f16x2 (v0 -> first element in memory)
__device__ __forceinline__ uint32_t cvt_h2(float v0, float v1) {
    uint32_t r;
    asm("cvt.rn.f16x2.f32 %0, %1, %2;" : "=r"(r) : "f"(v1), "f"(v0));
    return r;
}

// ---------------------------------------------------------------------------
// prep_w: transpose weights to [N][K], split fp32 -> fp16 hi/lo
// ---------------------------------------------------------------------------
extern "C" __global__ void prep_w(const float* __restrict__ pw1,
                                  const float* __restrict__ pw2,
                                  const float* __restrict__ pw3)
{
    int i = blockIdx.x * 256 + threadIdx.x;
    if (i >= 147456) return;
    float v; int dst;
    if (i < 16384) {            // pw1 [64][256] -> [256][64]
        int k = i >> 8, n = i & 255;
        v = pw1[i]; dst = WT1 + n * 64 + k;
    } else if (i < 81920) {     // pw2 [256][256]
        int j = i - 16384; int k = j >> 8, n = j & 255;
        v = pw2[j]; dst = WT2 + n * 256 + k;
    } else {                    // pw3 [256][256]
        int j = i - 81920; int k = j >> 8, n = j & 255;
        v = pw3[j]; dst = WT3 + n * 256 + k;
    }
    __half h = __float2half_rn(v);
    g_wt_hi[dst] = h;
    g_wt_lo[dst] = __float2half_rn(v - __half2float(h));
}

// ---------------------------------------------------------------------------
// prep_idx: per-batch compaction of valid row indices (order-preserving)
// ---------------------------------------------------------------------------
extern "C" __global__ void __launch_bounds__(256)
prep_idx(const int* __restrict__ mask)
{
    const int b = blockIdx.x, tid = threadIdx.x;
    const int lane = tid & 31, wid = tid >> 5;
    const int* mb = mask + b * N_;
    int v[4]; int c = 0;
#pragma unroll
    for (int i = 0; i < 4; i++) { v[i] = (mb[tid * 4 + i] != 0); c += v[i]; }
    int pre = c;
#pragma unroll
    for (int d = 1; d < 32; d <<= 1) {
        int t = __shfl_up_sync(0xffffffffu, pre, d);
        if (lane >= d) pre += t;
    }
    __shared__ int wsum[8];
    if (lane == 31) wsum[wid] = pre;
    __syncthreads();
    int wbase = 0;
#pragma unroll
    for (int w = 0; w < 8; w++)
        if (w < wid) wbase += wsum[w];
    int o = wbase + pre - c;
#pragma unroll
    for (int i = 0; i < 4; i++)
        if (v[i]) g_idx[b * N_ + (o++)] = tid * 4 + i;
    if (tid == 255) g_cnt[b] = wbase + pre;
}

// ---------------------------------------------------------------------------
// issue one B chunk (k32, Wh+Wl) via cp.async into buffer gi&1
// ---------------------------------------------------------------------------
__device__ __forceinline__ void issue_chunk(int gi, uint32_t sb, int tid)
{
    const __half *hi, *lo; int K, kc;
    if (gi < 2)       { hi = g_wt_hi + WT1; lo = g_wt_lo + WT1; K = 64;  kc = gi; }
    else if (gi < 10) { hi = g_wt_hi + WT2; lo = g_wt_lo + WT2; K = 256; kc = gi - 2; }
    else              { hi = g_wt_hi + WT3; lo = g_wt_lo + WT3; K = 256; kc = gi - 10; }
    int n = tid;
    uint32_t dst = sb + SM_B + (uint32_t)(gi & 1) * 32768u + (uint32_t)n * 128u;
    const char* sh = (const char*)(hi + (size_t)n * K + kc * 32);
    const char* sl = (const char*)(lo + (size_t)n * K + kc * 32);
#pragma unroll
    for (int c = 0; c < 4; c++)
        cpasync16(dst + ((uint32_t)(c ^ (n & 7)) << 4), sh + c * 16);
#pragma unroll
    for (int c = 0; c < 4; c++)
        cpasync16(dst + ((uint32_t)((c + 4) ^ (n & 7)) << 4), sl + c * 16);
}

// epilogue store into A smem (fp16), swizzled
__device__ __forceinline__ void store_one(char* smem, int row, int chunk, int t,
                                          float v0, float v1)
{
    uint32_t h2 = cvt_h2(v0, v1);
    uint32_t off = (uint32_t)row * 512u + ((uint32_t)(chunk ^ (row & 7)) << 4) + t * 4;
    *(uint32_t*)(smem + SM_A + off) = h2;
}

// ---------------------------------------------------------------------------
// phi kernel: gathered valid rows; fp16 A x (Wh+Wl) split weights + pool
// ---------------------------------------------------------------------------
extern "C" __global__ void __launch_bounds__(THREADS, 1)
phi_kernel(const float* __restrict__ x,
           const float* __restrict__ pb1, const float* __restrict__ pb2,
           const float* __restrict__ pb3)
{
    const int tile = blockIdx.x, b = blockIdx.y;
    const int cnt = g_cnt[b];
    if (tile * MT >= cnt) return;

    extern __shared__ char smem[];
    uint32_t sb = smem_u32(smem);
    const int tid = threadIdx.x, wid = tid >> 5, lane = tid & 31;
    const int m0 = wid * 16, gg = lane >> 2, t = lane & 3;

    ((float*)(smem + SM_BIAS))[tid]       = pb1[tid];
    ((float*)(smem + SM_BIAS))[256 + tid] = pb2[tid];
    ((float*)(smem + SM_BIAS))[512 + tid] = pb3[tid];

    // ---- gather x rows -> A smem fp16; zero padding slots
    {
        int row = tid >> 1, half = tid & 1;
        int slot = tile * MT + row;
        bool vld = slot < cnt;
        int r = vld ? g_idx[b * N_ + slot] : 0;
        const float4* src = (const float4*)(x +
            ((size_t)(b * N_ + r)) * DIN + half * 32);
        // 64 dims per row = 16 k8-chunks; this thread covers chunks half*8 .. half*8+7
        // write as two uint4 (4 chunks each)
#pragma unroll
        for (int q2 = 0; q2 < 2; q2++) {
            uint32_t h2[4];
            if (vld) {
#pragma unroll
                for (int p = 0; p < 4; p++) {
                    float4 a = src[q2 * 4 + p];
                    h2[p] = 0;   // placeholder, overwritten below
                    // pack 4 floats -> 2 h2 words? (handled below)
                    (void)a;
                }
            }
            // Each 16B smem chunk = 8 fp16 = 8 k-values = two float4 of source.
#pragma unroll
            for (int c = 0; c < 2; c++) {
                int kc = half * 4 + q2 * 2 + c;   // 16B chunk index within row (0..7)
                uint32_t off = (uint32_t)row * 512u + ((uint32_t)(kc ^ (row & 7)) << 4);
                if (vld) {
                    float4 a = src[(q2 * 2 + c) * 2];
                    float4 d = src[(q2 * 2 + c) * 2 + 1];
                    uint4 w;
                    w.x = cvt_h2(a.x, a.y);
                    w.y = cvt_h2(a.z, a.w);
                    w.z = cvt_h2(d.x, d.y);
                    w.w = cvt_h2(d.z, d.w);
                    *(uint4*)(smem + SM_A + off) = w;
                } else {
                    *(uint4*)(smem + SM_A + off) = make_uint4(0, 0, 0, 0);
                }
            }
        }
    }

    issue_chunk(0, sb, tid);
    CP_COMMIT();
    __syncthreads();

    float acc[32][4];
    int gi = 0;

    for (int l = 0; l < 3; l++) {
        const int nch = (l == 0) ? 2 : 8;
#pragma unroll
        for (int i = 0; i < 32; i++) {
            acc[i][0] = 0.f; acc[i][1] = 0.f; acc[i][2] = 0.f; acc[i][3] = 0.f;
        }
        for (int kc = 0; kc < nch; kc++) {
            if (gi + 1 < NCHUNKS) {
                issue_chunk(gi + 1, sb, tid);
                CP_COMMIT();
                CP_WAIT(1);
            } else {
                CP_WAIT(0);
            }
            __syncthreads();
            uint32_t bbase = sb + SM_B + (uint32_t)(gi & 1) * 32768u;
            uint32_t brow_ = (lane & 7) + ((lane >= 16) ? 8 : 0);
#pragma unroll
            for (int sc = 0; sc < 2; sc++) {
                int ks = kc * 2 + sc;
                uint32_t arow = m0 + (lane & 15);
                uint32_t achk = 2 * ks + (lane >> 4);
                uint32_t aoff = arow * 512u + (((achk ^ (arow & 7))) << 4);
                uint32_t a[4];
                ldm4(a, sb + SM_A + aoff);

                uint32_t chi = 2 * sc + ((lane >> 3) & 1);
                uint32_t clo = chi + 4;

                uint32_t bh[2][4], bl[2][4];
                {
                    uint32_t brow = brow_;
                    ldm4(bh[0], bbase + brow * 128u + ((chi ^ (brow & 7)) << 4));
                    ldm4(bl[0], bbase + brow * 128u + ((clo ^ (brow & 7)) << 4));
                }
#pragma unroll
                for (int nt = 0; nt < 16; nt++) {
                    int cur = nt & 1, nxt = cur ^ 1;
                    if (nt < 15) {
                        uint32_t brow = (nt + 1) * 16 + brow_;
                        ldm4(bh[nxt], bbase + brow * 128u + ((chi ^ (brow & 7)) << 4));
                        ldm4(bl[nxt], bbase + brow * 128u + ((clo ^ (brow & 7)) << 4));
                    }
                    mma16816(acc[2 * nt],     a, bh[cur][0], bh[cur][1]);
                    mma16816(acc[2 * nt],     a, bl[cur][0], bl[cur][1]);
                    mma16816(acc[2 * nt + 1], a, bh[cur][2], bh[cur][3]);
                    mma16816(acc[2 * nt + 1], a, bl[cur][2], bl[cur][3]);
                }
            }
            __syncthreads();
            gi++;
        }

        if (l < 2) {
            const float* bias = (const float*)(smem + SM_BIAS) + l * 256;
            int r0 = m0 + gg, r1 = r0 + 8;
#pragma unroll
            for (int nt = 0; nt < 16; nt++) {
                int n0 = nt * 16;
                float b0 = bias[n0 + 2 * t],     b1 = bias[n0 + 2 * t + 1];
                float b2 = bias[n0 + 8 + 2 * t], b3 = bias[n0 + 8 + 2 * t + 1];
                store_one(smem, r0, 2 * nt, t,
                          fmaxf(acc[2 * nt][0] + b0, 0.f),
                          fmaxf(acc[2 * nt][1] + b1, 0.f));
                store_one(smem, r1, 2 * nt, t,
                          fmaxf(acc[2 * nt][2] + b0, 0.f),
                          fmaxf(acc[2 * nt][3] + b1, 0.f));
                store_one(smem, r0, 2 * nt + 1, t,
                          fmaxf(acc[2 * nt + 1][0] + b2, 0.f),
                          fmaxf(acc[2 * nt + 1][1] + b3, 0.f));
                store_one(smem, r1, 2 * nt + 1, t,
                          fmaxf(acc[2 * nt + 1][2] + b2, 0.f),
                          fmaxf(acc[2 * nt + 1][3] + b3, 0.f));
            }
            __syncwarp();
        } else {
            const float* bias = (const float*)(smem + SM_BIAS) + 512;
            int r0 = m0 + gg, r1 = r0 + 8;
            float mv0 = (tile * MT + r0 < cnt) ? 1.f : 0.f;
            float mv1 = (tile * MT + r1 < cnt) ? 1.f : 0.f;
            float* pool = (float*)(smem + SM_POOL) + wid * 256;
#pragma unroll
            for (int nt = 0; nt < 16; nt++) {
                int n0 = nt * 16;
                float b0 = bias[n0 + 2 * t],     b1 = bias[n0 + 2 * t + 1];
                float b2 = bias[n0 + 8 + 2 * t], b3 = bias[n0 + 8 + 2 * t + 1];
                float s0 = mv0 * (acc[2 * nt][0] + b0) + mv1 * (acc[2 * nt][2] + b0);
                float s1 = mv0 * (acc[2 * nt][1] + b1) + mv1 * (acc[2 * nt][3] + b1);
                float s2 = mv0 * (acc[2 * nt + 1][0] + b2) + mv1 * (acc[2 * nt + 1][2] + b2);
                float s3 = mv0 * (acc[2 * nt + 1][1] + b3) + mv1 * (acc[2 * nt + 1][3] + b3);
#pragma unroll
                for (int d = 4; d < 32; d <<= 1) {
                    s0 += __shfl_xor_sync(0xffffffff, s0, d);
                    s1 += __shfl_xor_sync(0xffffffff, s1, d);
                    s2 += __shfl_xor_sync(0xffffffff, s2, d);
                    s3 += __shfl_xor_sync(0xffffffff, s3, d);
                }
                if (lane < 4) {
                    pool[n0 + 2 * t]         = s0;
                    pool[n0 + 2 * t + 1]     = s1;
                    pool[n0 + 8 + 2 * t]     = s2;
                    pool[n0 + 8 + 2 * t + 1] = s3;
                }
            }
            __syncthreads();
            float s = 0.f;
#pragma unroll
            for (int w = 0; w < 8; w++)
                s += ((const float*)(smem + SM_POOL))[w * 256 + tid];
            g_partial[(b * TILES + tile) * HID + tid] = s;
        }
    }
}

// ---------------------------------------------------------------------------
// rho kernel: 512 threads, split-k partials to break latency chains
// ---------------------------------------------------------------------------
extern "C" __global__ void __launch_bounds__(512)
rho_kernel(const float* __restrict__ rw1, const float* __restrict__ rb1,
           const float* __restrict__ rw2, const float* __restrict__ rb2,
           const float* __restrict__ rw3, const float* __restrict__ rb3,
           float* __restrict__ out)
{
    const int b   = blockIdx.x;
    const int tid = threadIdx.x;
    const int col = tid & 255, kh = tid >> 8;     // 2-way k split
    __shared__ float p[HID];
    __shared__ float o1[HID];
    __shared__ float part[512];

    const int cnt = g_cnt[b];
    const int nt  = (cnt + MT - 1) / MT;

    if (tid < 256) {
        float s = 0.f;
        for (int t = 0; t < nt; t++)
            s += g_partial[(b * TILES + t) * HID + tid];
        p[tid] = s;
    }
    __syncthreads();

    // layer 1: each half-thread sums 128 k's with 4 independent chains
    {
        const float* W = rw1 + (size_t)kh * 128 * HID + col;
        const float* pk = p + kh * 128;
        float a0 = 0.f, a1 = 0.f, a2 = 0.f, a3 = 0.f;
#pragma unroll 8
        for (int k = 0; k < 128; k += 4) {
            a0 = fmaf(pk[k],     W[(k)     * HID], a0);
            a1 = fmaf(pk[k + 1], W[(k + 1) * HID], a1);
            a2 = fmaf(pk[k + 2], W[(k + 2) * HID], a2);
            a3 = fmaf(pk[k + 3], W[(k + 3) * HID], a3);
        }
        part[tid] = (a0 + a1) + (a2 + a3);
    }
    __syncthreads();
    if (tid < 256)
        o1[tid] = fmaxf(part[tid] + part[tid + 256] + rb1[tid], 0.f);
    __syncthreads();

    // layer 2
    {
        const float* W = rw2 + (size_t)kh * 128 * HID + col;
        const float* pk = o1 + kh * 128;
        float a0 = 0.f, a1 = 0.f, a2 = 0.f, a3 = 0.f;
#pragma unroll 8
        for (int k = 0; k < 128; k += 4) {
            a0 = fmaf(pk[k],     W[(k)     * HID], a0);
            a1 = fmaf(pk[k + 1], W[(k + 1) * HID], a1);
            a2 = fmaf(pk[k + 2], W[(k + 2) * HID], a2);
            a3 = fmaf(pk[k + 3], W[(k + 3) * HID], a3);
        }
        part[tid] = (a0 + a1) + (a2 + a3);
    }
    __syncthreads();
    if (tid < 256)
        p[tid] = fmaxf(part[tid] + part[tid + 256] + rb2[tid], 0.f);
    __syncthreads();

    // layer 3: 128 cols, 4-way k split (64 k each)
    {
        const int c3 = tid & 127, k4 = tid >> 7;
        const float* W = rw3 + (size_t)k4 * 64 * DOUT + c3;
        const float* pk = p + k4 * 64;
        float a0 = 0.f, a1 = 0.f, a2 = 0.f, a3 = 0.f;
#pragma unroll 8
        for (int k = 0; k < 64; k += 4) {
            a0 = fmaf(pk[k],     W[(k)     * DOUT], a0);
            a1 = fmaf(pk[k + 1], W[(k + 1) * DOUT], a1);
            a2 = fmaf(pk[k + 2], W[(k + 2) * DOUT], a2);
            a3 = fmaf(pk[k + 3], W[(k + 3) * DOUT], a3);
        }
        part[tid] = (a0 + a1) + (a2 + a3);
    }
    __syncthreads();
    if (tid < DOUT) {
        float a3 = part[tid] + part[tid + 128] + part[tid + 256] + part[tid + 384]
                 + rb3[tid];
        out[b * DOUT + tid] = (cnt > 0) ? a3 : 0.f;
    }
}

// ---------------------------------------------------------------------------
extern "C" void kernel_launch(void* const* d_in, const int* in_sizes, int n_in,
                              void* d_out, int out_size)
{
    const float* x    = (const float*)d_in[0];
    const int*   mask = (const int*)  d_in[1];
    const float* pw1  = (const float*)d_in[2];
    const float* pb1  = (const float*)d_in[3];
    const float* pw2  = (const float*)d_in[4];
    const float* pb2  = (const float*)d_in[5];
    const float* pw3  = (const float*)d_in[6];
    const float* pb3  = (const float*)d_in[7];
    const float* rw1  = (const float*)d_in[8];
    const float* rb1  = (const float*)d_in[9];
    const float* rw2  = (const float*)d_in[10];
    const float* rb2  = (const float*)d_in[11];
    const float* rw3  = (const float*)d_in[12];
    const float* rb3  = (const float*)d_in[13];
    float* out = (float*)d_out;

    cudaFuncSetAttribute(phi_kernel,
                         cudaFuncAttributeMaxDynamicSharedMemorySize, SM_BYTES);

    prep_w<<<576, 256>>>(pw1, pw2, pw3);
    prep_idx<<<B_, 256>>>(mask);
    dim3 grid(TILES, B_);
    phi_kernel<<<grid, THREADS, SM_BYTES>>>(x, pb1, pb2, pb3);
    rho_kernel<<<B_, 512>>>(rw1, rb1, rw2, rb2, rw3, rb3, out);
}

// round 7
// speedup vs baseline: 17.6907x; 1.7416x over previous
#include <cuda_runtime.h>
#include <cuda_fp16.h>
#include <cstdint>

#define B_      256
#define N_      1024
#define DIN     64
#define HID     256
#define DOUT    128
#define MT      128
#define TILES   (N_ / MT)        // 8 (max tiles per batch)
#define THREADS 256
#define NCHUNKS 9                // k64 chunks: 1 (K=64) + 4 + 4

// smem layout (bytes)
#define SM_B     0                       // 2 buffers x 32768 (B: [256 n][128B = k64 fp16])
#define SM_BIAS  65536                   // 3 * 256 * 4
#define SM_POOL  68608                   // 8 * 256 * 4
#define SM_A     77824                   // A fp16: [128 m][512B row]
#define SM_BYTES (77824 + 65536)         // 143360

__device__ float g_partial[B_ * TILES * HID];
__device__ __align__(16) __half g_wt[147456];
__device__ int g_cnt[B_];
__device__ int g_idx[B_ * N_];
#define WT1 0
#define WT2 16384
#define WT3 81920

// ---------------------------------------------------------------------------
// helpers
// ---------------------------------------------------------------------------
__device__ __forceinline__ uint32_t smem_u32(const void* p) {
    uint32_t a;
    asm("{ .reg .u64 t; cvta.to.shared.u64 t, %1; cvt.u32.u64 %0, t; }"
        : "=r"(a) : "l"(p));
    return a;
}
__device__ __forceinline__ void ldm4(uint32_t r[4], uint32_t addr) {
    asm volatile("ldmatrix.sync.aligned.m8n8.x4.shared.b16 {%0,%1,%2,%3}, [%4];"
                 : "=r"(r[0]), "=r"(r[1]), "=r"(r[2]), "=r"(r[3]) : "r"(addr));
}
__device__ __forceinline__ void mma16816(float c[4], const uint32_t a[4],
                                         uint32_t b0, uint32_t b1) {
    asm volatile(
        "mma.sync.aligned.m16n8k16.row.col.f32.f16.f16.f32 "
        "{%0,%1,%2,%3}, {%4,%5,%6,%7}, {%8,%9}, {%0,%1,%2,%3};"
        : "+f"(c[0]), "+f"(c[1]), "+f"(c[2]), "+f"(c[3])
        : "r"(a[0]), "r"(a[1]), "r"(a[2]), "r"(a[3]), "r"(b0), "r"(b1));
}
__device__ __forceinline__ void cpasync16(uint32_t dst, const void* src) {
    asm volatile("cp.async.ca.shared.global [%0], [%1], 16;" :: "r"(dst), "l"(src));
}
#define CP_COMMIT() asm volatile("cp.async.commit_group;" ::: "memory")
#define CP_WAIT(N)  asm volatile("cp.async.wait_group %0;" :: "n"(N) : "memory")

// pack two fp32 -> f16x2 (v0 -> first element in memory)
__device__ __forceinline__ uint32_t cvt_h2(float v0, float v1) {
    uint32_t r;
    asm("cvt.rn.f16x2.f32 %0, %1, %2;" : "=r"(r) : "f"(v1), "f"(v0));
    return r;
}

// ---------------------------------------------------------------------------
// prep_w: transpose weights to [N][K], fp32 -> fp16
// ---------------------------------------------------------------------------
extern "C" __global__ void prep_w(const float* __restrict__ pw1,
                                  const float* __restrict__ pw2,
                                  const float* __restrict__ pw3)
{
    int i = blockIdx.x * 256 + threadIdx.x;
    if (i >= 147456) return;
    float v; int dst;
    if (i < 16384) {            // pw1 [64][256] -> [256][64]
        int k = i >> 8, n = i & 255;
        v = pw1[i]; dst = WT1 + n * 64 + k;
    } else if (i < 81920) {     // pw2 [256][256]
        int j = i - 16384; int k = j >> 8, n = j & 255;
        v = pw2[j]; dst = WT2 + n * 256 + k;
    } else {                    // pw3 [256][256]
        int j = i - 81920; int k = j >> 8, n = j & 255;
        v = pw3[j]; dst = WT3 + n * 256 + k;
    }
    g_wt[dst] = __float2half_rn(v);
}

// ---------------------------------------------------------------------------
// prep_idx: per-batch compaction of valid row indices (order-preserving)
// ---------------------------------------------------------------------------
extern "C" __global__ void __launch_bounds__(256)
prep_idx(const int* __restrict__ mask)
{
    const int b = blockIdx.x, tid = threadIdx.x;
    const int lane = tid & 31, wid = tid >> 5;
    const int* mb = mask + b * N_;
    int v[4]; int c = 0;
#pragma unroll
    for (int i = 0; i < 4; i++) { v[i] = (mb[tid * 4 + i] != 0); c += v[i]; }
    int pre = c;
#pragma unroll
    for (int d = 1; d < 32; d <<= 1) {
        int t = __shfl_up_sync(0xffffffffu, pre, d);
        if (lane >= d) pre += t;
    }
    __shared__ int wsum[8];
    if (lane == 31) wsum[wid] = pre;
    __syncthreads();
    int wbase = 0;
#pragma unroll
    for (int w = 0; w < 8; w++)
        if (w < wid) wbase += wsum[w];
    int o = wbase + pre - c;
#pragma unroll
    for (int i = 0; i < 4; i++)
        if (v[i]) g_idx[b * N_ + (o++)] = tid * 4 + i;
    if (tid == 255) g_cnt[b] = wbase + pre;
}

// ---------------------------------------------------------------------------
// issue one B chunk (k64) via cp.async into buffer gi&1
// row n = 128B (8 x 16B sub-chunks), sub-chunk c stored at c ^ (n&7)
// ---------------------------------------------------------------------------
__device__ __forceinline__ void issue_chunk(int gi, uint32_t sb, int tid)
{
    const __half* w; int K, kc;
    if (gi == 0)     { w = g_wt + WT1; K = 64;  kc = 0; }
    else if (gi < 5) { w = g_wt + WT2; K = 256; kc = gi - 1; }
    else             { w = g_wt + WT3; K = 256; kc = gi - 5; }
    int n = tid;
    uint32_t dst = sb + SM_B + (uint32_t)(gi & 1) * 32768u + (uint32_t)n * 128u;
    const char* src = (const char*)(w + (size_t)n * K + kc * 64);
#pragma unroll
    for (int c = 0; c < 8; c++)
        cpasync16(dst + ((uint32_t)(c ^ (n & 7)) << 4), src + c * 16);
}

// epilogue store into A smem (fp16), swizzled
__device__ __forceinline__ void store_one(char* smem, int row, int chunk, int t,
                                          float v0, float v1)
{
    uint32_t h2 = cvt_h2(v0, v1);
    uint32_t off = (uint32_t)row * 512u + ((uint32_t)(chunk ^ (row & 7)) << 4) + t * 4;
    *(uint32_t*)(smem + SM_A + off) = h2;
}

// ---------------------------------------------------------------------------
// phi kernel: gathered valid rows; fp16 x fp16 MMA + pool
// ---------------------------------------------------------------------------
extern "C" __global__ void __launch_bounds__(THREADS, 1)
phi_kernel(const float* __restrict__ x,
           const float* __restrict__ pb1, const float* __restrict__ pb2,
           const float* __restrict__ pb3)
{
    const int tile = blockIdx.x, b = blockIdx.y;
    const int cnt = g_cnt[b];
    if (tile * MT >= cnt) return;

    extern __shared__ char smem[];
    uint32_t sb = smem_u32(smem);
    const int tid = threadIdx.x, wid = tid >> 5, lane = tid & 31;
    const int m0 = wid * 16, gg = lane >> 2, t = lane & 3;

    ((float*)(smem + SM_BIAS))[tid]       = pb1[tid];
    ((float*)(smem + SM_BIAS))[256 + tid] = pb2[tid];
    ((float*)(smem + SM_BIAS))[512 + tid] = pb3[tid];

    // ---- gather x rows -> A smem fp16; zero padding slots
    {
        int row = tid >> 1, half = tid & 1;
        int slot = tile * MT + row;
        bool vld = slot < cnt;
        int r = vld ? g_idx[b * N_ + slot] : 0;
        const float4* src = (const float4*)(x +
            ((size_t)(b * N_ + r)) * DIN + half * 32);
#pragma unroll
        for (int c = 0; c < 4; c++) {
            int kc = half * 4 + c;   // 16B chunk index within row (0..7)
            uint32_t off = (uint32_t)row * 512u + ((uint32_t)(kc ^ (row & 7)) << 4);
            if (vld) {
                float4 a = src[c * 2];
                float4 d = src[c * 2 + 1];
                uint4 w;
                w.x = cvt_h2(a.x, a.y);
                w.y = cvt_h2(a.z, a.w);
                w.z = cvt_h2(d.x, d.y);
                w.w = cvt_h2(d.z, d.w);
                *(uint4*)(smem + SM_A + off) = w;
            } else {
                *(uint4*)(smem + SM_A + off) = make_uint4(0, 0, 0, 0);
            }
        }
    }

    issue_chunk(0, sb, tid);
    CP_COMMIT();
    __syncthreads();

    float acc[32][4];
    int gi = 0;

    for (int l = 0; l < 3; l++) {
        const int nch = (l == 0) ? 1 : 4;
#pragma unroll
        for (int i = 0; i < 32; i++) {
            acc[i][0] = 0.f; acc[i][1] = 0.f; acc[i][2] = 0.f; acc[i][3] = 0.f;
        }
        for (int kc = 0; kc < nch; kc++) {
            if (gi + 1 < NCHUNKS) {
                issue_chunk(gi + 1, sb, tid);
                CP_COMMIT();
                CP_WAIT(1);
            } else {
                CP_WAIT(0);
            }
            __syncthreads();             // chunk gi ready in buf gi&1
            uint32_t bbase = sb + SM_B + (uint32_t)(gi & 1) * 32768u;
            uint32_t brow_ = (lane & 7) + ((lane >= 16) ? 8 : 0);
#pragma unroll
            for (int sc = 0; sc < 4; sc++) {
                int ks = kc * 4 + sc;        // k16 index within layer
                uint32_t arow = m0 + (lane & 15);
                uint32_t achk = 2 * ks + (lane >> 4);
                uint32_t aoff = arow * 512u + (((achk ^ (arow & 7))) << 4);
                uint32_t a[4];
                ldm4(a, sb + SM_A + aoff);

                uint32_t chi = 2 * sc + ((lane >> 3) & 1);   // 16B sub-chunk in B row

                uint32_t bh[2][4];
                {
                    uint32_t brow = brow_;
                    ldm4(bh[0], bbase + brow * 128u + ((chi ^ (brow & 7)) << 4));
                }
#pragma unroll
                for (int nt = 0; nt < 16; nt++) {
                    int cur = nt & 1, nxt = cur ^ 1;
                    if (nt < 15) {
                        uint32_t brow = (nt + 1) * 16 + brow_;
                        ldm4(bh[nxt], bbase + brow * 128u + ((chi ^ (brow & 7)) << 4));
                    }
                    mma16816(acc[2 * nt],     a, bh[cur][0], bh[cur][1]);
                    mma16816(acc[2 * nt + 1], a, bh[cur][2], bh[cur][3]);
                }
            }
            __syncthreads();             // compute done before buf reuse
            gi++;
        }

        if (l < 2) {
            const float* bias = (const float*)(smem + SM_BIAS) + l * 256;
            int r0 = m0 + gg, r1 = r0 + 8;
#pragma unroll
            for (int nt = 0; nt < 16; nt++) {
                int n0 = nt * 16;
                float b0 = bias[n0 + 2 * t],     b1 = bias[n0 + 2 * t + 1];
                float b2 = bias[n0 + 8 + 2 * t], b3 = bias[n0 + 8 + 2 * t + 1];
                store_one(smem, r0, 2 * nt, t,
                          fmaxf(acc[2 * nt][0] + b0, 0.f),
                          fmaxf(acc[2 * nt][1] + b1, 0.f));
                store_one(smem, r1, 2 * nt, t,
                          fmaxf(acc[2 * nt][2] + b0, 0.f),
                          fmaxf(acc[2 * nt][3] + b1, 0.f));
                store_one(smem, r0, 2 * nt + 1, t,
                          fmaxf(acc[2 * nt + 1][0] + b2, 0.f),
                          fmaxf(acc[2 * nt + 1][1] + b3, 0.f));
                store_one(smem, r1, 2 * nt + 1, t,
                          fmaxf(acc[2 * nt + 1][2] + b2, 0.f),
                          fmaxf(acc[2 * nt + 1][3] + b3, 0.f));
            }
            __syncwarp();
        } else {
            const float* bias = (const float*)(smem + SM_BIAS) + 512;
            int r0 = m0 + gg, r1 = r0 + 8;
            float mv0 = (tile * MT + r0 < cnt) ? 1.f : 0.f;
            float mv1 = (tile * MT + r1 < cnt) ? 1.f : 0.f;
            float* pool = (float*)(smem + SM_POOL) + wid * 256;
#pragma unroll
            for (int nt = 0; nt < 16; nt++) {
                int n0 = nt * 16;
                float b0 = bias[n0 + 2 * t],     b1 = bias[n0 + 2 * t + 1];
                float b2 = bias[n0 + 8 + 2 * t], b3 = bias[n0 + 8 + 2 * t + 1];
                float s0 = mv0 * (acc[2 * nt][0] + b0) + mv1 * (acc[2 * nt][2] + b0);
                float s1 = mv0 * (acc[2 * nt][1] + b1) + mv1 * (acc[2 * nt][3] + b1);
                float s2 = mv0 * (acc[2 * nt + 1][0] + b2) + mv1 * (acc[2 * nt + 1][2] + b2);
                float s3 = mv0 * (acc[2 * nt + 1][1] + b3) + mv1 * (acc[2 * nt + 1][3] + b3);
#pragma unroll
                for (int d = 4; d < 32; d <<= 1) {
                    s0 += __shfl_xor_sync(0xffffffff, s0, d);
                    s1 += __shfl_xor_sync(0xffffffff, s1, d);
                    s2 += __shfl_xor_sync(0xffffffff, s2, d);
                    s3 += __shfl_xor_sync(0xffffffff, s3, d);
                }
                if (lane < 4) {
                    pool[n0 + 2 * t]         = s0;
                    pool[n0 + 2 * t + 1]     = s1;
                    pool[n0 + 8 + 2 * t]     = s2;
                    pool[n0 + 8 + 2 * t + 1] = s3;
                }
            }
            __syncthreads();
            float s = 0.f;
#pragma unroll
            for (int w = 0; w < 8; w++)
                s += ((const float*)(smem + SM_POOL))[w * 256 + tid];
            g_partial[(b * TILES + tile) * HID + tid] = s;
        }
    }
}

// ---------------------------------------------------------------------------
// rho kernel: 512 threads, split-k partials to break latency chains
// ---------------------------------------------------------------------------
extern "C" __global__ void __launch_bounds__(512)
rho_kernel(const float* __restrict__ rw1, const float* __restrict__ rb1,
           const float* __restrict__ rw2, const float* __restrict__ rb2,
           const float* __restrict__ rw3, const float* __restrict__ rb3,
           float* __restrict__ out)
{
    const int b   = blockIdx.x;
    const int tid = threadIdx.x;
    const int col = tid & 255, kh = tid >> 8;     // 2-way k split
    __shared__ float p[HID];
    __shared__ float o1[HID];
    __shared__ float part[512];

    const int cnt = g_cnt[b];
    const int nt  = (cnt + MT - 1) / MT;

    if (tid < 256) {
        float s = 0.f;
        for (int t = 0; t < nt; t++)
            s += g_partial[(b * TILES + t) * HID + tid];
        p[tid] = s;
    }
    __syncthreads();

    {
        const float* W = rw1 + (size_t)kh * 128 * HID + col;
        const float* pk = p + kh * 128;
        float a0 = 0.f, a1 = 0.f, a2 = 0.f, a3 = 0.f;
#pragma unroll 8
        for (int k = 0; k < 128; k += 4) {
            a0 = fmaf(pk[k],     W[(k)     * HID], a0);
            a1 = fmaf(pk[k + 1], W[(k + 1) * HID], a1);
            a2 = fmaf(pk[k + 2], W[(k + 2) * HID], a2);
            a3 = fmaf(pk[k + 3], W[(k + 3) * HID], a3);
        }
        part[tid] = (a0 + a1) + (a2 + a3);
    }
    __syncthreads();
    if (tid < 256)
        o1[tid] = fmaxf(part[tid] + part[tid + 256] + rb1[tid], 0.f);
    __syncthreads();

    {
        const float* W = rw2 + (size_t)kh * 128 * HID + col;
        const float* pk = o1 + kh * 128;
        float a0 = 0.f, a1 = 0.f, a2 = 0.f, a3 = 0.f;
#pragma unroll 8
        for (int k = 0; k < 128; k += 4) {
            a0 = fmaf(pk[k],     W[(k)     * HID], a0);
            a1 = fmaf(pk[k + 1], W[(k + 1) * HID], a1);
            a2 = fmaf(pk[k + 2], W[(k + 2) * HID], a2);
            a3 = fmaf(pk[k + 3], W[(k + 3) * HID], a3);
        }
        part[tid] = (a0 + a1) + (a2 + a3);
    }
    __syncthreads();
    if (tid < 256)
        p[tid] = fmaxf(part[tid] + part[tid + 256] + rb2[tid], 0.f);
    __syncthreads();

    {
        const int c3 = tid & 127, k4 = tid >> 7;
        const float* W = rw3 + (size_t)k4 * 64 * DOUT + c3;
        const float* pk = p + k4 * 64;
        float a0 = 0.f, a1 = 0.f, a2 = 0.f, a3 = 0.f;
#pragma unroll 8
        for (int k = 0; k < 64; k += 4) {
            a0 = fmaf(pk[k],     W[(k)     * DOUT], a0);
            a1 = fmaf(pk[k + 1], W[(k + 1) * DOUT], a1);
            a2 = fmaf(pk[k + 2], W[(k + 2) * DOUT], a2);
            a3 = fmaf(pk[k + 3], W[(k + 3) * DOUT], a3);
        }
        part[tid] = (a0 + a1) + (a2 + a3);
    }
    __syncthreads();
    if (tid < DOUT) {
        float a3 = part[tid] + part[tid + 128] + part[tid + 256] + part[tid + 384]
                 + rb3[tid];
        out[b * DOUT + tid] = (cnt > 0) ? a3 : 0.f;
    }
}

// ---------------------------------------------------------------------------
extern "C" void kernel_launch(void* const* d_in, const int* in_sizes, int n_in,
                              void* d_out, int out_size)
{
    const float* x    = (const float*)d_in[0];
    const int*   mask = (const int*)  d_in[1];
    const float* pw1  = (const float*)d_in[2];
    const float* pb1  = (const float*)d_in[3];
    const float* pw2  = (const float*)d_in[4];
    const float* pb2  = (const float*)d_in[5];
    const float* pw3  = (const float*)d_in[6];
    const float* pb3  = (const float*)d_in[7];
    const float* rw1  = (const float*)d_in[8];
    const float* rb1  = (const float*)d_in[9];
    const float* rw2  = (const float*)d_in[10];
    const float* rb2  = (const float*)d_in[11];
    const float* rw3  = (const float*)d_in[12];
    const float* rb3  = (const float*)d_in[13];
    float* out = (float*)d_out;

    cudaFuncSetAttribute(phi_kernel,
                         cudaFuncAttributeMaxDynamicSharedMemorySize, SM_BYTES);

    prep_w<<<576, 256>>>(pw1, pw2, pw3);
    prep_idx<<<B_, 256>>>(mask);
    dim3 grid(TILES, B_);
    phi_kernel<<<grid, THREADS, SM_BYTES>>>(x, pb1, pb2, pb3);
    rho_kernel<<<B_, 512>>>(rw1, rb1, rw2, rb2, rw3, rb3, out);
}

// round 8
// speedup vs baseline: 18.4792x; 1.0446x over previous
#include <cuda_runtime.h>
#include <cuda_fp16.h>
#include <cstdint>

#define B_      256
#define N_      1024
#define DIN     64
#define HID     256
#define DOUT    128
#define MT      128
#define TILES   (N_ / MT)        // 8 (max tiles per batch)
#define THREADS 256
#define NCHUNKS 9                // k64 chunks: 1 (K=64) + 4 + 4

// smem layout (bytes)
#define SM_B     0                       // 3 buffers x 32768 (B: [256 n][128B = k64 fp16])
#define SM_BIAS  98304                   // 3 * 256 * 4
#define SM_POOL  101376                  // 8 * 256 * 4
#define SM_A     109568                  // A fp16: [128 m][512B row]
#define SM_BYTES (109568 + 65536)        // 175104

__device__ float g_partial[B_ * TILES * HID];
__device__ __align__(16) __half g_wt[147456];
__device__ int g_cnt[B_];
__device__ int g_idx[B_ * N_];
#define WT1 0
#define WT2 16384
#define WT3 81920

// ---------------------------------------------------------------------------
// helpers
// ---------------------------------------------------------------------------
__device__ __forceinline__ uint32_t smem_u32(const void* p) {
    uint32_t a;
    asm("{ .reg .u64 t; cvta.to.shared.u64 t, %1; cvt.u32.u64 %0, t; }"
        : "=r"(a) : "l"(p));
    return a;
}
__device__ __forceinline__ void ldm4(uint32_t r[4], uint32_t addr) {
    asm volatile("ldmatrix.sync.aligned.m8n8.x4.shared.b16 {%0,%1,%2,%3}, [%4];"
                 : "=r"(r[0]), "=r"(r[1]), "=r"(r[2]), "=r"(r[3]) : "r"(addr));
}
__device__ __forceinline__ void mma16816(float c[4], const uint32_t a[4],
                                         uint32_t b0, uint32_t b1) {
    asm volatile(
        "mma.sync.aligned.m16n8k16.row.col.f32.f16.f16.f32 "
        "{%0,%1,%2,%3}, {%4,%5,%6,%7}, {%8,%9}, {%0,%1,%2,%3};"
        : "+f"(c[0]), "+f"(c[1]), "+f"(c[2]), "+f"(c[3])
        : "r"(a[0]), "r"(a[1]), "r"(a[2]), "r"(a[3]), "r"(b0), "r"(b1));
}
__device__ __forceinline__ void cpasync16(uint32_t dst, const void* src) {
    asm volatile("cp.async.ca.shared.global [%0], [%1], 16;" :: "r"(dst), "l"(src));
}
#define CP_COMMIT() asm volatile("cp.async.commit_group;" ::: "memory")
#define CP_WAIT(N)  asm volatile("cp.async.wait_group %0;" :: "n"(N) : "memory")

// pack two fp32 -> f16x2 (v0 -> first element in memory)
__device__ __forceinline__ uint32_t cvt_h2(float v0, float v1) {
    uint32_t r;
    asm("cvt.rn.f16x2.f32 %0, %1, %2;" : "=r"(r) : "f"(v1), "f"(v0));
    return r;
}

// ---------------------------------------------------------------------------
// prep: blocks 0..575 transpose+convert weights; blocks 576..831 compact mask
// ---------------------------------------------------------------------------
extern "C" __global__ void __launch_bounds__(256)
prep_all(const float* __restrict__ pw1, const float* __restrict__ pw2,
         const float* __restrict__ pw3, const int* __restrict__ mask)
{
    if (blockIdx.x < 576) {
        int i = blockIdx.x * 256 + threadIdx.x;
        if (i >= 147456) return;
        float v; int dst;
        if (i < 16384) {            // pw1 [64][256] -> [256][64]
            int k = i >> 8, n = i & 255;
            v = pw1[i]; dst = WT1 + n * 64 + k;
        } else if (i < 81920) {     // pw2 [256][256]
            int j = i - 16384; int k = j >> 8, n = j & 255;
            v = pw2[j]; dst = WT2 + n * 256 + k;
        } else {                    // pw3 [256][256]
            int j = i - 81920; int k = j >> 8, n = j & 255;
            v = pw3[j]; dst = WT3 + n * 256 + k;
        }
        g_wt[dst] = __float2half_rn(v);
    } else {
        const int b = blockIdx.x - 576, tid = threadIdx.x;
        const int lane = tid & 31, wid = tid >> 5;
        const int* mb = mask + b * N_;
        int v[4]; int c = 0;
#pragma unroll
        for (int i = 0; i < 4; i++) { v[i] = (mb[tid * 4 + i] != 0); c += v[i]; }
        int pre = c;
#pragma unroll
        for (int d = 1; d < 32; d <<= 1) {
            int t = __shfl_up_sync(0xffffffffu, pre, d);
            if (lane >= d) pre += t;
        }
        __shared__ int wsum[8];
        if (lane == 31) wsum[wid] = pre;
        __syncthreads();
        int wbase = 0;
#pragma unroll
        for (int w = 0; w < 8; w++)
            if (w < wid) wbase += wsum[w];
        int o = wbase + pre - c;
#pragma unroll
        for (int i = 0; i < 4; i++)
            if (v[i]) g_idx[b * N_ + (o++)] = tid * 4 + i;
        if (tid == 255) g_cnt[b] = wbase + pre;
    }
}

// ---------------------------------------------------------------------------
// issue one B chunk (k64) via cp.async into ring buffer gi%3
// row n = 128B (8 x 16B sub-chunks), sub-chunk c stored at c ^ (n&7)
// ---------------------------------------------------------------------------
__device__ __forceinline__ void issue_chunk(int gi, uint32_t sb, int tid)
{
    const __half* w; int K, kc;
    if (gi == 0)     { w = g_wt + WT1; K = 64;  kc = 0; }
    else if (gi < 5) { w = g_wt + WT2; K = 256; kc = gi - 1; }
    else             { w = g_wt + WT3; K = 256; kc = gi - 5; }
    int n = tid;
    uint32_t dst = sb + SM_B + (uint32_t)(gi % 3) * 32768u + (uint32_t)n * 128u;
    const char* src = (const char*)(w + (size_t)n * K + kc * 64);
#pragma unroll
    for (int c = 0; c < 8; c++)
        cpasync16(dst + ((uint32_t)(c ^ (n & 7)) << 4), src + c * 16);
}

// epilogue store into A smem (fp16), swizzled
__device__ __forceinline__ void store_one(char* smem, int row, int chunk, int t,
                                          float v0, float v1)
{
    uint32_t h2 = cvt_h2(v0, v1);
    uint32_t off = (uint32_t)row * 512u + ((uint32_t)(chunk ^ (row & 7)) << 4) + t * 4;
    *(uint32_t*)(smem + SM_A + off) = h2;
}

// ---------------------------------------------------------------------------
// phi kernel: gathered valid rows; fp16 x fp16 MMA + pool
// ---------------------------------------------------------------------------
extern "C" __global__ void __launch_bounds__(THREADS, 1)
phi_kernel(const float* __restrict__ x,
           const float* __restrict__ pb1, const float* __restrict__ pb2,
           const float* __restrict__ pb3)
{
    const int tile = blockIdx.x, b = blockIdx.y;
    const int cnt = g_cnt[b];
    if (tile * MT >= cnt) return;

    extern __shared__ char smem[];
    uint32_t sb = smem_u32(smem);
    const int tid = threadIdx.x, wid = tid >> 5, lane = tid & 31;
    const int m0 = wid * 16, gg = lane >> 2, t = lane & 3;

    // issue chunk 0 as early as possible
    issue_chunk(0, sb, tid);
    CP_COMMIT();

    ((float*)(smem + SM_BIAS))[tid]       = pb1[tid];
    ((float*)(smem + SM_BIAS))[256 + tid] = pb2[tid];
    ((float*)(smem + SM_BIAS))[512 + tid] = pb3[tid];

    // ---- gather x rows -> A smem fp16; zero padding slots
    {
        int row = tid >> 1, half = tid & 1;
        int slot = tile * MT + row;
        bool vld = slot < cnt;
        int r = vld ? g_idx[b * N_ + slot] : 0;
        const float4* src = (const float4*)(x +
            ((size_t)(b * N_ + r)) * DIN + half * 32);
#pragma unroll
        for (int c = 0; c < 4; c++) {
            int kc = half * 4 + c;   // 16B chunk index within row (0..7)
            uint32_t off = (uint32_t)row * 512u + ((uint32_t)(kc ^ (row & 7)) << 4);
            if (vld) {
                float4 a = src[c * 2];
                float4 d = src[c * 2 + 1];
                uint4 w;
                w.x = cvt_h2(a.x, a.y);
                w.y = cvt_h2(a.z, a.w);
                w.z = cvt_h2(d.x, d.y);
                w.w = cvt_h2(d.z, d.w);
                *(uint4*)(smem + SM_A + off) = w;
            } else {
                *(uint4*)(smem + SM_A + off) = make_uint4(0, 0, 0, 0);
            }
        }
    }

    float acc[32][4];
    int gi = 0;

    for (int l = 0; l < 3; l++) {
        const int nch = (l == 0) ? 1 : 4;
#pragma unroll
        for (int i = 0; i < 32; i++) {
            acc[i][0] = 0.f; acc[i][1] = 0.f; acc[i][2] = 0.f; acc[i][3] = 0.f;
        }
        for (int kc = 0; kc < nch; kc++) {
            // issue next chunk into ring slot (gi+1)%3 — that slot's last
            // compute finished before the PREVIOUS iteration's barrier.
            if (gi + 1 < NCHUNKS) {
                issue_chunk(gi + 1, sb, tid);
                CP_COMMIT();
                CP_WAIT(1);              // chunk gi complete (gi+1 in flight)
            } else {
                CP_WAIT(0);
            }
            __syncthreads();             // publish chunk gi; also fences
                                         // prior compute/epilogue smem writes
            uint32_t bbase = sb + SM_B + (uint32_t)(gi % 3) * 32768u;
            uint32_t brow_ = (lane & 7) + ((lane >= 16) ? 8 : 0);
#pragma unroll
            for (int sc = 0; sc < 4; sc++) {
                int ks = kc * 4 + sc;        // k16 index within layer
                uint32_t arow = m0 + (lane & 15);
                uint32_t achk = 2 * ks + (lane >> 4);
                uint32_t aoff = arow * 512u + (((achk ^ (arow & 7))) << 4);
                uint32_t a[4];
                ldm4(a, sb + SM_A + aoff);

                uint32_t chi = 2 * sc + ((lane >> 3) & 1);   // 16B sub-chunk in B row

                uint32_t bh[2][4];
                {
                    uint32_t brow = brow_;
                    ldm4(bh[0], bbase + brow * 128u + ((chi ^ (brow & 7)) << 4));
                }
#pragma unroll
                for (int nt = 0; nt < 16; nt++) {
                    int cur = nt & 1, nxt = cur ^ 1;
                    if (nt < 15) {
                        uint32_t brow = (nt + 1) * 16 + brow_;
                        ldm4(bh[nxt], bbase + brow * 128u + ((chi ^ (brow & 7)) << 4));
                    }
                    mma16816(acc[2 * nt],     a, bh[cur][0], bh[cur][1]);
                    mma16816(acc[2 * nt + 1], a, bh[cur][2], bh[cur][3]);
                }
            }
            gi++;
        }

        if (l < 2) {
            const float* bias = (const float*)(smem + SM_BIAS) + l * 256;
            int r0 = m0 + gg, r1 = r0 + 8;
#pragma unroll
            for (int nt = 0; nt < 16; nt++) {
                int n0 = nt * 16;
                float b0 = bias[n0 + 2 * t],     b1 = bias[n0 + 2 * t + 1];
                float b2 = bias[n0 + 8 + 2 * t], b3 = bias[n0 + 8 + 2 * t + 1];
                store_one(smem, r0, 2 * nt, t,
                          fmaxf(acc[2 * nt][0] + b0, 0.f),
                          fmaxf(acc[2 * nt][1] + b1, 0.f));
                store_one(smem, r1, 2 * nt, t,
                          fmaxf(acc[2 * nt][2] + b0, 0.f),
                          fmaxf(acc[2 * nt][3] + b1, 0.f));
                store_one(smem, r0, 2 * nt + 1, t,
                          fmaxf(acc[2 * nt + 1][0] + b2, 0.f),
                          fmaxf(acc[2 * nt + 1][1] + b3, 0.f));
                store_one(smem, r1, 2 * nt + 1, t,
                          fmaxf(acc[2 * nt + 1][2] + b2, 0.f),
                          fmaxf(acc[2 * nt + 1][3] + b3, 0.f));
            }
            __syncwarp();   // each warp reads only its own 16 A rows next layer
        } else {
            const float* bias = (const float*)(smem + SM_BIAS) + 512;
            int r0 = m0 + gg, r1 = r0 + 8;
            float mv0 = (tile * MT + r0 < cnt) ? 1.f : 0.f;
            float mv1 = (tile * MT + r1 < cnt) ? 1.f : 0.f;
            float* pool = (float*)(smem + SM_POOL) + wid * 256;
#pragma unroll
            for (int nt = 0; nt < 16; nt++) {
                int n0 = nt * 16;
                float b0 = bias[n0 + 2 * t],     b1 = bias[n0 + 2 * t + 1];
                float b2 = bias[n0 + 8 + 2 * t], b3 = bias[n0 + 8 + 2 * t + 1];
                float s0 = mv0 * (acc[2 * nt][0] + b0) + mv1 * (acc[2 * nt][2] + b0);
                float s1 = mv0 * (acc[2 * nt][1] + b1) + mv1 * (acc[2 * nt][3] + b1);
                float s2 = mv0 * (acc[2 * nt + 1][0] + b2) + mv1 * (acc[2 * nt + 1][2] + b2);
                float s3 = mv0 * (acc[2 * nt + 1][1] + b3) + mv1 * (acc[2 * nt + 1][3] + b3);
#pragma unroll
                for (int d = 4; d < 32; d <<= 1) {
                    s0 += __shfl_xor_sync(0xffffffff, s0, d);
                    s1 += __shfl_xor_sync(0xffffffff, s1, d);
                    s2 += __shfl_xor_sync(0xffffffff, s2, d);
                    s3 += __shfl_xor_sync(0xffffffff, s3, d);
                }
                if (lane < 4) {
                    pool[n0 + 2 * t]         = s0;
                    pool[n0 + 2 * t + 1]     = s1;
                    pool[n0 + 8 + 2 * t]     = s2;
                    pool[n0 + 8 + 2 * t + 1] = s3;
                }
            }
            __syncthreads();
            float s = 0.f;
#pragma unroll
            for (int w = 0; w < 8; w++)
                s += ((const float*)(smem + SM_POOL))[w * 256 + tid];
            g_partial[(b * TILES + tile) * HID + tid] = s;
        }
    }
}

// ---------------------------------------------------------------------------
// rho kernel: 512 threads, split-k partials; MLP-8 partial gather
// ---------------------------------------------------------------------------
extern "C" __global__ void __launch_bounds__(512, 2)
rho_kernel(const float* __restrict__ rw1, const float* __restrict__ rb1,
           const float* __restrict__ rw2, const float* __restrict__ rb2,
           const float* __restrict__ rw3, const float* __restrict__ rb3,
           float* __restrict__ out)
{
    const int b   = blockIdx.x;
    const int tid = threadIdx.x;
    const int col = tid & 255, kh = tid >> 8;     // 2-way k split
    __shared__ float p[HID];
    __shared__ float o1[HID];
    __shared__ float part[512];

    const int cnt = g_cnt[b];
    const int ntile = (cnt + MT - 1) / MT;

    if (tid < 256) {
        // fixed unroll with predication -> all live loads issued back-to-back
        float s = 0.f;
        const float* gp = g_partial + (size_t)b * TILES * HID + tid;
#pragma unroll
        for (int t = 0; t < TILES; t++) {
            float v = (t < ntile) ? gp[t * HID] : 0.f;
            s += v;
        }
        p[tid] = s;
    }
    __syncthreads();

    {
        const float* W = rw1 + (size_t)kh * 128 * HID + col;
        const float* pk = p + kh * 128;
        float a0 = 0.f, a1 = 0.f, a2 = 0.f, a3 = 0.f;
#pragma unroll 8
        for (int k = 0; k < 128; k += 4) {
            a0 = fmaf(pk[k],     W[(k)     * HID], a0);
            a1 = fmaf(pk[k + 1], W[(k + 1) * HID], a1);
            a2 = fmaf(pk[k + 2], W[(k + 2) * HID], a2);
            a3 = fmaf(pk[k + 3], W[(k + 3) * HID], a3);
        }
        part[tid] = (a0 + a1) + (a2 + a3);
    }
    __syncthreads();
    if (tid < 256)
        o1[tid] = fmaxf(part[tid] + part[tid + 256] + rb1[tid], 0.f);
    __syncthreads();

    {
        const float* W = rw2 + (size_t)kh * 128 * HID + col;
        const float* pk = o1 + kh * 128;
        float a0 = 0.f, a1 = 0.f, a2 = 0.f, a3 = 0.f;
#pragma unroll 8
        for (int k = 0; k < 128; k += 4) {
            a0 = fmaf(pk[k],     W[(k)     * HID], a0);
            a1 = fmaf(pk[k + 1], W[(k + 1) * HID], a1);
            a2 = fmaf(pk[k + 2], W[(k + 2) * HID], a2);
            a3 = fmaf(pk[k + 3], W[(k + 3) * HID], a3);
        }
        part[tid] = (a0 + a1) + (a2 + a3);
    }
    __syncthreads();
    if (tid < 256)
        p[tid] = fmaxf(part[tid] + part[tid + 256] + rb2[tid], 0.f);
    __syncthreads();

    {
        const int c3 = tid & 127, k4 = tid >> 7;
        const float* W = rw3 + (size_t)k4 * 64 * DOUT + c3;
        const float* pk = p + k4 * 64;
        float a0 = 0.f, a1 = 0.f, a2 = 0.f, a3 = 0.f;
#pragma unroll 8
        for (int k = 0; k < 64; k += 4) {
            a0 = fmaf(pk[k],     W[(k)     * DOUT], a0);
            a1 = fmaf(pk[k + 1], W[(k + 1) * DOUT], a1);
            a2 = fmaf(pk[k + 2], W[(k + 2) * DOUT], a2);
            a3 = fmaf(pk[k + 3], W[(k + 3) * DOUT], a3);
        }
        part[tid] = (a0 + a1) + (a2 + a3);
    }
    __syncthreads();
    if (tid < DOUT) {
        float a3 = part[tid] + part[tid + 128] + part[tid + 256] + part[tid + 384]
                 + rb3[tid];
        out[b * DOUT + tid] = (cnt > 0) ? a3 : 0.f;
    }
}

// ---------------------------------------------------------------------------
extern "C" void kernel_launch(void* const* d_in, const int* in_sizes, int n_in,
                              void* d_out, int out_size)
{
    const float* x    = (const float*)d_in[0];
    const int*   mask = (const int*)  d_in[1];
    const float* pw1  = (const float*)d_in[2];
    const float* pb1  = (const float*)d_in[3];
    const float* pw2  = (const float*)d_in[4];
    const float* pb2  = (const float*)d_in[5];
    const float* pw3  = (const float*)d_in[6];
    const float* pb3  = (const float*)d_in[7];
    const float* rw1  = (const float*)d_in[8];
    const float* rb1  = (const float*)d_in[9];
    const float* rw2  = (const float*)d_in[10];
    const float* rb2  = (const float*)d_in[11];
    const float* rw3  = (const float*)d_in[12];
    const float* rb3  = (const float*)d_in[13];
    float* out = (float*)d_out;

    cudaFuncSetAttribute(phi_kernel,
                         cudaFuncAttributeMaxDynamicSharedMemorySize, SM_BYTES);

    prep_all<<<832, 256>>>(pw1, pw2, pw3, mask);
    dim3 grid(TILES, B_);
    phi_kernel<<<grid, THREADS, SM_BYTES>>>(x, pb1, pb2, pb3);
    rho_kernel<<<B_, 512>>>(rw1, rb1, rw2, rb2, rw3, rb3, out);
}